// round 12
// baseline (speedup 1.0000x reference)
#include <cuda_runtime.h>
#include <cuda_bf16.h>
#include <cstdint>
#include <cstdio>

#define E_DIM 1024
#define H_DIM 1024
#define VOC   32000
#define T_STEPS 64
#define NBLK  128
#define NGATE 4096
#define NWGRP 4096000          // fc_W 8-float groups

// -------- device scratch --------
__device__ float g_X[T_STEPS * E_DIM];
__device__ float g_hpub[(T_STEPS + 1) * H_DIM];
__device__ float g_Xg[T_STEPS * NGATE];
__device__ unsigned int g_cnt;
// pre-split, pre-swizzled fc_W and hs (bf16 hi/lo), R4 layout
__device__ __nv_bfloat16 g_Whi[(size_t)VOC * E_DIM];
__device__ __nv_bfloat16 g_Wlo[(size_t)VOC * E_DIM];
__device__ __nv_bfloat16 g_Bhi[T_STEPS * H_DIM];
__device__ __nv_bfloat16 g_Blo[T_STEPS * H_DIM];

__device__ __forceinline__ float sigmoidf_(float x) { return 1.f / (1.f + __expf(-x)); }
__device__ __forceinline__ float tanhf_(float x) {
    return __fdividef(2.f, 1.f + __expf(-2.f * x)) - 1.f;
}

// ---- packed f32x2 helpers ----
__device__ __forceinline__ void fma2(unsigned long long& d,
                                     unsigned long long a, unsigned long long b) {
    asm("fma.rn.f32x2 %0, %1, %2, %0;" : "+l"(d) : "l"(a), "l"(b));
}
__device__ __forceinline__ float sum2(unsigned long long v) {
    float lo, hi;
    asm("mov.b64 {%0, %1}, %2;" : "=f"(lo), "=f"(hi) : "l"(v));
    return lo + hi;
}
__device__ __forceinline__ void ld2u64(const void* p, unsigned long long& a,
                                       unsigned long long& b) {
    asm("ld.global.v2.u64 {%0, %1}, [%2];" : "=l"(a), "=l"(b) : "l"(p));
}
__device__ __forceinline__ void ld2u64_cg(const void* p, unsigned long long& a,
                                          unsigned long long& b) {
    asm("ld.global.cg.v2.u64 {%0, %1}, [%2];" : "=l"(a), "=l"(b) : "l"(p));
}

// ---- bf16 split helpers ----
__device__ __forceinline__ void split2(float2 a, uint32_t& hi, uint32_t& lo) {
    __nv_bfloat162 h = __float22bfloat162_rn(a);
    float2 f = __bfloat1622float2(h);
    __nv_bfloat162 l2 = __float22bfloat162_rn(make_float2(a.x - f.x, a.y - f.y));
    hi = *reinterpret_cast<uint32_t*>(&h);
    lo = *reinterpret_cast<uint32_t*>(&l2);
}
__device__ __forceinline__ void split4(float4 a, uint2& hi, uint2& lo) {
    split2(make_float2(a.x, a.y), hi.x, lo.x);
    split2(make_float2(a.z, a.w), hi.y, lo.y);
}

// =====================================================================
// K0: build X, init h row 0 + counter
// =====================================================================
__global__ void prep_kernel(const int* __restrict__ captions,
                            const float* __restrict__ features,
                            const float* __restrict__ etab) {
    int t = blockIdx.x;
    const float* src = (t == 0) ? features : (etab + (size_t)captions[t - 1] * E_DIM);
    for (int k = threadIdx.x; k < E_DIM; k += blockDim.x)
        g_X[t * E_DIM + k] = src[k];
    if (t == 0) {
        for (int k = threadIdx.x; k < H_DIM; k += blockDim.x) g_hpub[k] = 0.f;
        if (threadIdx.x == 0) g_cnt = 0u;
    }
}

// ======================= shared GEMM helpers =========================
#define FC_M    128
#define FC_NCH  16
#define SWZ(x) ((x) ^ (((x) >> 3) & 0x70))

__device__ __forceinline__ uint32_t smem_u32(const void* p) {
    uint32_t a;
    asm("{ .reg .u64 t; cvta.to.shared.u64 t, %1; cvt.u32.u64 %0, t; }" : "=r"(a) : "l"(p));
    return a;
}

#define CP16(dst, src) \
    asm volatile("cp.async.cg.shared.global [%0], [%1], 16;" :: "r"(dst), "l"(src) : "memory")
#define CP_COMMIT() asm volatile("cp.async.commit_group;" ::: "memory")
#define CP_WAIT(n)  asm volatile("cp.async.wait_group %0;" :: "n"(n) : "memory")

#define LDM_X4(r, a)                                                          \
    asm volatile("ldmatrix.sync.aligned.m8n8.x4.shared.b16 {%0,%1,%2,%3}, [%4];" \
        : "=r"((r)[0]), "=r"((r)[1]), "=r"((r)[2]), "=r"((r)[3]) : "r"(a))

#define MMA16816(d, a, b0, b1)                                                \
    asm volatile("mma.sync.aligned.m16n8k16.row.col.f32.bf16.bf16.f32 "       \
        "{%0,%1,%2,%3},{%4,%5,%6,%7},{%8,%9},{%0,%1,%2,%3};"                  \
        : "+f"((d)[0]), "+f"((d)[1]), "+f"((d)[2]), "+f"((d)[3])              \
        : "r"((a)[0]), "r"((a)[1]), "r"((a)[2]), "r"((a)[3]),                 \
          "r"(b0), "r"(b1))

// =====================================================================
// K1: Xg = X @ W_ih^T + bias (32 CTAs) — fused-convert body (R11 proven).
// =====================================================================
#define XGO_AF32(b) ((b) * 32768)
#define XGO_AHI     65536
#define XGO_ALO     81920
#define XGO_BHI     98304
#define XGO_BLO     106496
#define XG_SMEM     114688

__device__ __forceinline__ int xg_dst(int r, int t) {
    return t * NGATE + (((r & 1023) >> 3) << 5) + ((r >> 10) << 3) + (r & 7);
}

__global__ void __launch_bounds__(128, 2)
xg_mma_kernel(const float* __restrict__ Wih,
              const float* __restrict__ bih, const float* __restrict__ bhh) {
    extern __shared__ __align__(1024) char smem[];
    const uint32_t sb = smem_u32(smem);

    const int tid  = threadIdx.x;
    const int wid  = tid >> 5;
    const int lane = tid & 31;
    const int vbase = blockIdx.x * FC_M;
    const int m0 = wid * 32;

    const int a_row  = m0 + (lane & 15);
    const uint32_t a_roff = (uint32_t)a_row * 128;
    const uint32_t a_xor  = (uint32_t)(a_row & 7) << 4;
    const uint32_t a_kh   = (uint32_t)(lane >> 4) * 16;
    const int b_rsub = (lane & 7) + ((lane >> 4) & 1) * 8;
    const uint32_t b_xor = (uint32_t)(lane & 7) << 4;
    const uint32_t b_kh  = (uint32_t)((lane >> 3) & 1) * 16;

    float acc[2][8][4];
#pragma unroll
    for (int mt = 0; mt < 2; mt++)
#pragma unroll
        for (int nt = 0; nt < 8; nt++)
#pragma unroll
            for (int q = 0; q < 4; q++) acc[mt][nt][q] = 0.f;

    auto issue = [&](int c) {
        const uint32_t dbase = sb + XGO_AF32(c & 1);
#pragma unroll
        for (int p = 0; p < 16; p++) {
            int idx = tid + p * 128;
            int row = idx >> 4, seg = idx & 15;
            const char* src = (const char*)(Wih + (size_t)(vbase + row) * E_DIM + c * 64)
                              + seg * 16;
            CP16(dbase + (uint32_t)(row * 256 + seg * 16), src);
        }
        CP_COMMIT();
    };

    issue(0);
    issue(1);

    for (int c = 0; c < FC_NCH; c++) {
        if (c < FC_NCH - 1) { CP_WAIT(1); } else { CP_WAIT(0); }
        __syncthreads();

        {
            const char* af = smem + XGO_AF32(c & 1);
#pragma unroll
            for (int p = 0; p < 32; p++) {
                int fidx = tid + p * 128;
                int row = fidx >> 5, kp = fidx & 31;
                float2 a = *(const float2*)(af + row * 256 + kp * 8);
                uint32_t hi, lo; split2(a, hi, lo);
                uint32_t off = SWZ((uint32_t)(row * 128 + kp * 4));
                *(uint32_t*)(smem + XGO_AHI + off) = hi;
                *(uint32_t*)(smem + XGO_ALO + off) = lo;
            }
        }
        {
#pragma unroll
            for (int p = 0; p < 16; p++) {
                int fidx = tid + p * 128;
                int row = fidx >> 5, kp = fidx & 31;
                float2 a = *(const float2*)(g_X + row * E_DIM + c * 64 + kp * 2);
                uint32_t hi, lo; split2(a, hi, lo);
                uint32_t off = SWZ((uint32_t)(row * 128 + kp * 4));
                *(uint32_t*)(smem + XGO_BHI + off) = hi;
                *(uint32_t*)(smem + XGO_BLO + off) = lo;
            }
        }
        __syncthreads();

        if (c + 2 < FC_NCH) issue(c + 2);

        const uint32_t sAhi = sb + XGO_AHI, sAlo = sb + XGO_ALO;
        const uint32_t sBhi = sb + XGO_BHI, sBlo = sb + XGO_BLO;
#pragma unroll
        for (int ks = 0; ks < 4; ks++) {
            const uint32_t akb = (uint32_t)(ks * 32) + a_kh;
            const uint32_t bkb = (uint32_t)(ks * 32) + b_kh;

            uint32_t ah[2][4], al[2][4];
#pragma unroll
            for (int mt = 0; mt < 2; mt++) {
                uint32_t off = a_roff + (uint32_t)(mt * 16 * 128) + (akb ^ a_xor);
                LDM_X4(ah[mt], sAhi + off);
                LDM_X4(al[mt], sAlo + off);
            }
            uint32_t bh[4][4], bl[4][4];
#pragma unroll
            for (int bp = 0; bp < 4; bp++) {
                uint32_t n = (uint32_t)(bp * 16 + b_rsub);
                uint32_t off = n * 128 + (bkb ^ b_xor);
                LDM_X4(bh[bp], sBhi + off);
                LDM_X4(bl[bp], sBlo + off);
            }
#pragma unroll
            for (int mt = 0; mt < 2; mt++)
#pragma unroll
                for (int nt = 0; nt < 8; nt++) {
                    const int bp = nt >> 1, sel = (nt & 1) * 2;
                    MMA16816(acc[mt][nt], ah[mt], bh[bp][sel], bh[bp][sel + 1]);
                    MMA16816(acc[mt][nt], al[mt], bh[bp][sel], bh[bp][sel + 1]);
                    MMA16816(acc[mt][nt], ah[mt], bl[bp][sel], bl[bp][sel + 1]);
                }
        }
    }

    const int g  = lane >> 2;
    const int t4 = lane & 3;
#pragma unroll
    for (int mt = 0; mt < 2; mt++) {
        int r0 = vbase + m0 + mt * 16 + g;
        float bv0 = bih[r0] + bhh[r0];
        float bv8 = bih[r0 + 8] + bhh[r0 + 8];
#pragma unroll
        for (int nt = 0; nt < 8; nt++) {
            int t0 = nt * 8 + t4 * 2;
            g_Xg[xg_dst(r0,     t0)]     = acc[mt][nt][0] + bv0;
            g_Xg[xg_dst(r0,     t0 + 1)] = acc[mt][nt][1] + bv0;
            g_Xg[xg_dst(r0 + 8, t0)]     = acc[mt][nt][2] + bv8;
            g_Xg[xg_dst(r0 + 8, t0 + 1)] = acc[mt][nt][3] + bv8;
        }
    }
}

// =====================================================================
// K2: persistent LSTM recurrence + hidden fc_W split.
// Per step, each thread converts one 8-float fc_W group -> g_Whi/g_Wlo
// during the barrier-wait dead time. Tail: split hs -> g_Bhi/g_Blo.
// =====================================================================
__global__ void __launch_bounds__(512, 1)
lstm_kernel(const float* __restrict__ Whh, const float* __restrict__ fcW) {
    __shared__ float partA[16][32];

    const int tid = threadIdx.x;
    const int w   = tid >> 5;
    const int l   = tid & 31;
    const int j   = tid & 7;
    const int c   = tid >> 3;
    const int b   = blockIdx.x;
    const int jg  = b * 8 + j;

    float creg = 0.f;

    unsigned long long wreg2[4][8];
#pragma unroll
    for (int g = 0; g < 4; g++) {
        const char* p = (const char*)(Whh + (size_t)(g * H_DIM + jg) * H_DIM + c * 16);
#pragma unroll
        for (int q = 0; q < 4; q++)
            ld2u64(p + q * 16, wreg2[g][2*q], wreg2[g][2*q+1]);
    }
    __syncthreads();

    for (int t = 0; t < T_STEPS; t++) {
        float xgv = 0.f;
        if (tid < 32)
            xgv = __ldcg(&g_Xg[t * NGATE + b * 32 + tid]);

        // ---- critical h load first ----
        unsigned long long hv2[8];
        {
            const char* hp = (const char*)(g_hpub + t * H_DIM + c * 16);
#pragma unroll
            for (int q = 0; q < 4; q++)
                ld2u64_cg(hp + q * 16, hv2[2*q], hv2[2*q+1]);
        }

        // ---- hidden splitW: load one 8-float group (latency hidden) ----
        const int widx = (t * NBLK + b) * 512 + tid;
        const bool wvalid = (widx < NWGRP);
        float4 wa0, wa1;
        int wrow = 0, wcc = 0, wsub = 0;
        if (wvalid) {
            wrow = widx >> 7;
            int gg = widx & 127;
            wcc = gg >> 3; wsub = gg & 7;
            const float4* src = (const float4*)(fcW + ((size_t)wrow << 10)
                                                + (wcc << 6) + (wsub << 3));
            wa0 = __ldg(src);
            wa1 = __ldg(src + 1);
        }

        float part[4];
#pragma unroll
        for (int g = 0; g < 4; g++) {
            unsigned long long acc = 0ull;
#pragma unroll
            for (int i = 0; i < 8; i++) fma2(acc, wreg2[g][i], hv2[i]);
            part[g] = sum2(acc);
        }
#pragma unroll
        for (int g = 0; g < 4; g++) {
            part[g] += __shfl_xor_sync(0xffffffffu, part[g], 8);
            part[g] += __shfl_xor_sync(0xffffffffu, part[g], 16);
        }
        if (l < 8) {
#pragma unroll
            for (int g = 0; g < 4; g++) partA[w][g * 8 + l] = part[g];
        }
        __syncthreads();                          // sync1

        if (tid < 32) {
            float s = xgv;
#pragma unroll
            for (int ww = 0; ww < 16; ww++) s += partA[ww][tid];

            const int jj = tid & 7;
            float sf = __shfl_sync(0xffffffffu, s, jj + 8);
            float sg = __shfl_sync(0xffffffffu, s, jj + 16);
            float so = __shfl_sync(0xffffffffu, s, jj + 24);

            if (tid < 8) {
                float ii = sigmoidf_(s);
                float ff = sigmoidf_(sf);
                float gg = tanhf_(sg);
                float oo = sigmoidf_(so);
                float cc = ff * creg + ii * gg;
                creg = cc;
                float hn = oo * tanhf_(cc);
                g_hpub[(t + 1) * H_DIM + b * 8 + tid] = hn;
            }
            __syncwarp();
            if (tid == 0) {
                asm volatile("red.release.gpu.global.add.u32 [%0], 1;"
                             :: "l"(&g_cnt) : "memory");
            }
        }

        // splitW convert+store in the dead time (all threads; warp0 after
        // its publish tail, warps>=1 immediately)
        if (wvalid) {
            uint2 h0, l0, h1, l1;
            split4(wa0, h0, l0);
            split4(wa1, h1, l1);
            size_t dst = ((size_t)wrow * 16 + wcc) * 64
                       + (size_t)((wsub ^ (wrow & 7)) << 3);
            *(uint4*)(g_Whi + dst) = make_uint4(h0.x, h0.y, h1.x, h1.y);
            *(uint4*)(g_Wlo + dst) = make_uint4(l0.x, l0.y, l1.x, l1.y);
        }

        if (tid == 32) {
            // poll every step (incl. last: tail below reads all rows)
            const unsigned int target = (unsigned)NBLK * (unsigned)(t + 1);
            unsigned int v;
            do {
                asm volatile("ld.acquire.gpu.u32 %0, [%1];"
                             : "=r"(v) : "l"(&g_cnt) : "memory");
            } while (v < target);
        }
        __syncthreads();                          // sync_final
    }

    // ---- tail: split hs rows (g_hpub 1..64) -> g_Bhi/g_Blo, pre-swizzled ----
    {
        int idx = b * 512 + tid;          // 0..65535
        int t = idx >> 10;
        int e = idx & 1023;
        int cc2 = e >> 6, ee = e & 63;
        float v = __ldcg(&g_hpub[(t + 1) * H_DIM + e]);
        __nv_bfloat16 hb = __float2bfloat16(v);
        float hf = __bfloat162float(hb);
        __nv_bfloat16 lb = __float2bfloat16(v - hf);
        size_t dst = ((size_t)t * 16 + cc2) * 64 + (((ee >> 3) ^ (t & 7)) << 3) + (ee & 7);
        g_Bhi[dst] = hb;
        g_Blo[dst] = lb;
    }
}

// =====================================================================
// K3: fc GEMM — R4 pure-bf16 version (proven 40.5us): cp.async of
// pre-split, pre-swizzled tiles, double-buffered, no in-kernel convert.
// =====================================================================
#define FCB_AHI(b) ((b) * 16384)
#define FCB_ALO(b) (32768 + (b) * 16384)
#define FCB_BHI(b) (65536 + (b) * 8192)
#define FCB_BLO(b) (81920 + (b) * 8192)
#define FC_SMEM    98304

__global__ void __launch_bounds__(128, 2)
fc_mma_kernel(const float* __restrict__ fcb, float* __restrict__ out) {
    extern __shared__ __align__(1024) char smem[];
    const uint32_t sb = smem_u32(smem);

    const int tid  = threadIdx.x;
    const int wid  = tid >> 5;
    const int lane = tid & 31;
    const int vbase = blockIdx.x * FC_M;
    const int m0 = wid * 32;

    const int a_row  = m0 + (lane & 15);
    const uint32_t a_roff = (uint32_t)a_row * 128;
    const uint32_t a_xor  = (uint32_t)(a_row & 7) << 4;
    const uint32_t a_kh   = (uint32_t)(lane >> 4) * 16;
    const int b_rsub = (lane & 7) + ((lane >> 4) & 1) * 8;
    const uint32_t b_xor = (uint32_t)(lane & 7) << 4;
    const uint32_t b_kh  = (uint32_t)((lane >> 3) & 1) * 16;

    float acc[2][8][4];
#pragma unroll
    for (int mt = 0; mt < 2; mt++)
#pragma unroll
        for (int nt = 0; nt < 8; nt++)
#pragma unroll
            for (int q = 0; q < 4; q++) acc[mt][nt][q] = 0.f;

    auto issue = [&](int c, int buf) {
#pragma unroll
        for (int p = 0; p < 16; p++) {           // A: 2048 x 16B
            int idx = tid + p * 128;
            int hl  = idx >> 10;
            int row = (idx >> 3) & 127;
            int seg = idx & 7;
            const char* src = (const char*)(hl ? g_Wlo : g_Whi)
                + (((size_t)(vbase + row) * 16 + c) * 128 + seg * 16);
            uint32_t dst = sb + (hl ? FCB_ALO(buf) : FCB_AHI(buf)) + row * 128 + seg * 16;
            CP16(dst, src);
        }
#pragma unroll
        for (int p = 0; p < 8; p++) {            // B: 1024 x 16B
            int idx = tid + p * 128;
            int hl  = idx >> 9;
            int row = (idx >> 3) & 63;
            int seg = idx & 7;
            const char* src = (const char*)(hl ? g_Blo : g_Bhi)
                + (((size_t)row * 16 + c) * 128 + seg * 16);
            uint32_t dst = sb + (hl ? FCB_BLO(buf) : FCB_BHI(buf)) + row * 128 + seg * 16;
            CP16(dst, src);
        }
        CP_COMMIT();
    };

    issue(0, 0);
    issue(1, 1);

    for (int c = 0; c < FC_NCH; c++) {
        if (c < FC_NCH - 1) { CP_WAIT(1); } else { CP_WAIT(0); }
        __syncthreads();

        const int buf = c & 1;
        const uint32_t sAhi = sb + FCB_AHI(buf);
        const uint32_t sAlo = sb + FCB_ALO(buf);
        const uint32_t sBhi = sb + FCB_BHI(buf);
        const uint32_t sBlo = sb + FCB_BLO(buf);

#pragma unroll
        for (int ks = 0; ks < 4; ks++) {
            const uint32_t akb = (uint32_t)(ks * 32) + a_kh;
            const uint32_t bkb = (uint32_t)(ks * 32) + b_kh;

            uint32_t ah[2][4], al[2][4];
#pragma unroll
            for (int mt = 0; mt < 2; mt++) {
                uint32_t off = a_roff + (uint32_t)(mt * 16 * 128) + (akb ^ a_xor);
                LDM_X4(ah[mt], sAhi + off);
                LDM_X4(al[mt], sAlo + off);
            }
            uint32_t bh[4][4], bl[4][4];
#pragma unroll
            for (int bp = 0; bp < 4; bp++) {
                uint32_t n = (uint32_t)(bp * 16 + b_rsub);
                uint32_t off = n * 128 + (bkb ^ b_xor);
                LDM_X4(bh[bp], sBhi + off);
                LDM_X4(bl[bp], sBlo + off);
            }
#pragma unroll
            for (int mt = 0; mt < 2; mt++)
#pragma unroll
                for (int nt = 0; nt < 8; nt++) {
                    const int bp = nt >> 1, sel = (nt & 1) * 2;
                    MMA16816(acc[mt][nt], ah[mt], bh[bp][sel], bh[bp][sel + 1]);
                    MMA16816(acc[mt][nt], al[mt], bh[bp][sel], bh[bp][sel + 1]);
                    MMA16816(acc[mt][nt], ah[mt], bl[bp][sel], bl[bp][sel + 1]);
                }
        }
        __syncthreads();
        if (c + 2 < FC_NCH) issue(c + 2, buf);
    }

    const int g  = lane >> 2;
    const int t4 = lane & 3;
#pragma unroll
    for (int mt = 0; mt < 2; mt++) {
        int v0 = vbase + m0 + mt * 16 + g;
        float bv0 = fcb[v0];
        float bv8 = fcb[v0 + 8];
#pragma unroll
        for (int nt = 0; nt < 8; nt++) {
            int t0 = nt * 8 + t4 * 2;
            out[(size_t)t0 * VOC + v0]           = acc[mt][nt][0] + bv0;
            out[(size_t)(t0 + 1) * VOC + v0]     = acc[mt][nt][1] + bv0;
            out[(size_t)t0 * VOC + v0 + 8]       = acc[mt][nt][2] + bv8;
            out[(size_t)(t0 + 1) * VOC + v0 + 8] = acc[mt][nt][3] + bv8;
        }
    }
}

// =====================================================================
// launch
// =====================================================================
extern "C" void kernel_launch(void* const* d_in, const int* in_sizes, int n_in,
                              void* d_out, int out_size) {
    const int*   captions = (const int*)  d_in[0];
    const float* features = (const float*)d_in[1];
    const float* etab     = (const float*)d_in[2];
    const float* W_ih     = (const float*)d_in[3];
    const float* W_hh     = (const float*)d_in[4];
    const float* b_ih     = (const float*)d_in[5];
    const float* b_hh     = (const float*)d_in[6];
    const float* fc_W     = (const float*)d_in[7];
    const float* fc_b     = (const float*)d_in[8];
    float* out = (float*)d_out;

    cudaFuncSetAttribute(xg_mma_kernel,
                         cudaFuncAttributeMaxDynamicSharedMemorySize, XG_SMEM);
    cudaFuncSetAttribute(fc_mma_kernel,
                         cudaFuncAttributeMaxDynamicSharedMemorySize, FC_SMEM);

    prep_kernel<<<T_STEPS, 256>>>(captions, features, etab);
    xg_mma_kernel<<<NGATE / FC_M, 128, XG_SMEM>>>(W_ih, b_ih, b_hh);
    lstm_kernel<<<NBLK, 512>>>(W_hh, fc_W);
    fc_mma_kernel<<<VOC / FC_M, 128, FC_SMEM>>>(fc_b, out);
}

// round 13
// speedup vs baseline: 1.4129x; 1.4129x over previous
#include <cuda_runtime.h>
#include <cuda_bf16.h>
#include <cstdint>
#include <cstdio>

#define E_DIM 1024
#define H_DIM 1024
#define VOC   32000
#define T_STEPS 64
#define NBLK  128
#define NGATE 4096
#define NWLINES 1024000u       // fc_W 128B lines (32000*1024*4/128)

// -------- device scratch --------
__device__ float g_X[T_STEPS * E_DIM];
__device__ float g_hpub[(T_STEPS + 1) * H_DIM];
__device__ float g_Xg[T_STEPS * NGATE];
__device__ unsigned int g_cnt;

__device__ __forceinline__ float sigmoidf_(float x) { return 1.f / (1.f + __expf(-x)); }
__device__ __forceinline__ float tanhf_(float x) {
    return __fdividef(2.f, 1.f + __expf(-2.f * x)) - 1.f;
}

// ---- packed f32x2 helpers ----
__device__ __forceinline__ void fma2(unsigned long long& d,
                                     unsigned long long a, unsigned long long b) {
    asm("fma.rn.f32x2 %0, %1, %2, %0;" : "+l"(d) : "l"(a), "l"(b));
}
__device__ __forceinline__ float sum2(unsigned long long v) {
    float lo, hi;
    asm("mov.b64 {%0, %1}, %2;" : "=f"(lo), "=f"(hi) : "l"(v));
    return lo + hi;
}
__device__ __forceinline__ void ld2u64(const void* p, unsigned long long& a,
                                       unsigned long long& b) {
    asm("ld.global.v2.u64 {%0, %1}, [%2];" : "=l"(a), "=l"(b) : "l"(p));
}
__device__ __forceinline__ void ld2u64_cg(const void* p, unsigned long long& a,
                                          unsigned long long& b) {
    asm("ld.global.cg.v2.u64 {%0, %1}, [%2];" : "=l"(a), "=l"(b) : "l"(p));
}

// =====================================================================
// K0: build X, init h row 0 + counter
// =====================================================================
__global__ void prep_kernel(const int* __restrict__ captions,
                            const float* __restrict__ features,
                            const float* __restrict__ etab) {
    int t = blockIdx.x;
    const float* src = (t == 0) ? features : (etab + (size_t)captions[t - 1] * E_DIM);
    for (int k = threadIdx.x; k < E_DIM; k += blockDim.x)
        g_X[t * E_DIM + k] = src[k];
    if (t == 0) {
        for (int k = threadIdx.x; k < H_DIM; k += blockDim.x) g_hpub[k] = 0.f;
        if (threadIdx.x == 0) g_cnt = 0u;
    }
}

// ======================= shared GEMM helpers =========================
#define FC_M    128
#define FC_NCH  16

#define FCO_AF32(b) ((b) * 32768)
#define FCO_AHI     65536
#define FCO_ALO     81920
#define FCO_BHI     98304
#define FCO_BLO     106496
#define FC_SMEM     114688      // 112 KB -> 2 CTAs/SM

#define SWZ(x) ((x) ^ (((x) >> 3) & 0x70))

__device__ __forceinline__ uint32_t smem_u32(const void* p) {
    uint32_t a;
    asm("{ .reg .u64 t; cvta.to.shared.u64 t, %1; cvt.u32.u64 %0, t; }" : "=r"(a) : "l"(p));
    return a;
}

__device__ __forceinline__ void split2(float2 a, uint32_t& hi, uint32_t& lo) {
    __nv_bfloat162 h = __float22bfloat162_rn(a);
    float2 f = __bfloat1622float2(h);
    __nv_bfloat162 l2 = __float22bfloat162_rn(make_float2(a.x - f.x, a.y - f.y));
    hi = *reinterpret_cast<uint32_t*>(&h);
    lo = *reinterpret_cast<uint32_t*>(&l2);
}

#define CP16(dst, src) \
    asm volatile("cp.async.cg.shared.global [%0], [%1], 16;" :: "r"(dst), "l"(src) : "memory")
#define CP_COMMIT() asm volatile("cp.async.commit_group;" ::: "memory")
#define CP_WAIT(n)  asm volatile("cp.async.wait_group %0;" :: "n"(n) : "memory")

#define LDM_X4(r, a)                                                          \
    asm volatile("ldmatrix.sync.aligned.m8n8.x4.shared.b16 {%0,%1,%2,%3}, [%4];" \
        : "=r"((r)[0]), "=r"((r)[1]), "=r"((r)[2]), "=r"((r)[3]) : "r"(a))

#define MMA16816(d, a, b0, b1)                                                \
    asm volatile("mma.sync.aligned.m16n8k16.row.col.f32.bf16.bf16.f32 "       \
        "{%0,%1,%2,%3},{%4,%5,%6,%7},{%8,%9},{%0,%1,%2,%3};"                  \
        : "+f"((d)[0]), "+f"((d)[1]), "+f"((d)[2]), "+f"((d)[3])              \
        : "r"((a)[0]), "r"((a)[1]), "r"((a)[2]), "r"((a)[3]),                 \
          "r"(b0), "r"(b1))

// =====================================================================
// K1: Xg = X @ W_ih^T + bias (32 CTAs) — fused-convert body (proven).
// =====================================================================
__device__ __forceinline__ int xg_dst(int r, int t) {
    return t * NGATE + (((r & 1023) >> 3) << 5) + ((r >> 10) << 3) + (r & 7);
}

__global__ void __launch_bounds__(128, 2)
xg_mma_kernel(const float* __restrict__ Wih,
              const float* __restrict__ bih, const float* __restrict__ bhh) {
    extern __shared__ __align__(1024) char smem[];
    const uint32_t sb = smem_u32(smem);

    const int tid  = threadIdx.x;
    const int wid  = tid >> 5;
    const int lane = tid & 31;
    const int vbase = blockIdx.x * FC_M;
    const int m0 = wid * 32;

    const int a_row  = m0 + (lane & 15);
    const uint32_t a_roff = (uint32_t)a_row * 128;
    const uint32_t a_xor  = (uint32_t)(a_row & 7) << 4;
    const uint32_t a_kh   = (uint32_t)(lane >> 4) * 16;
    const int b_rsub = (lane & 7) + ((lane >> 4) & 1) * 8;
    const uint32_t b_xor = (uint32_t)(lane & 7) << 4;
    const uint32_t b_kh  = (uint32_t)((lane >> 3) & 1) * 16;

    float acc[2][8][4];
#pragma unroll
    for (int mt = 0; mt < 2; mt++)
#pragma unroll
        for (int nt = 0; nt < 8; nt++)
#pragma unroll
            for (int q = 0; q < 4; q++) acc[mt][nt][q] = 0.f;

    auto issue = [&](int c) {
        const uint32_t dbase = sb + FCO_AF32(c & 1);
#pragma unroll
        for (int p = 0; p < 16; p++) {
            int idx = tid + p * 128;
            int row = idx >> 4, seg = idx & 15;
            const char* src = (const char*)(Wih + (size_t)(vbase + row) * E_DIM + c * 64)
                              + seg * 16;
            CP16(dbase + (uint32_t)(row * 256 + seg * 16), src);
        }
        CP_COMMIT();
    };

    issue(0);
    issue(1);

    for (int c = 0; c < FC_NCH; c++) {
        if (c < FC_NCH - 1) { CP_WAIT(1); } else { CP_WAIT(0); }
        __syncthreads();

        {
            const char* af = smem + FCO_AF32(c & 1);
#pragma unroll
            for (int p = 0; p < 32; p++) {
                int fidx = tid + p * 128;
                int row = fidx >> 5, kp = fidx & 31;
                float2 a = *(const float2*)(af + row * 256 + kp * 8);
                uint32_t hi, lo; split2(a, hi, lo);
                uint32_t off = SWZ((uint32_t)(row * 128 + kp * 4));
                *(uint32_t*)(smem + FCO_AHI + off) = hi;
                *(uint32_t*)(smem + FCO_ALO + off) = lo;
            }
        }
        {
#pragma unroll
            for (int p = 0; p < 16; p++) {
                int fidx = tid + p * 128;
                int row = fidx >> 5, kp = fidx & 31;
                float2 a = *(const float2*)(g_X + row * E_DIM + c * 64 + kp * 2);
                uint32_t hi, lo; split2(a, hi, lo);
                uint32_t off = SWZ((uint32_t)(row * 128 + kp * 4));
                *(uint32_t*)(smem + FCO_BHI + off) = hi;
                *(uint32_t*)(smem + FCO_BLO + off) = lo;
            }
        }
        __syncthreads();

        if (c + 2 < FC_NCH) issue(c + 2);

        const uint32_t sAhi = sb + FCO_AHI, sAlo = sb + FCO_ALO;
        const uint32_t sBhi = sb + FCO_BHI, sBlo = sb + FCO_BLO;
#pragma unroll
        for (int ks = 0; ks < 4; ks++) {
            const uint32_t akb = (uint32_t)(ks * 32) + a_kh;
            const uint32_t bkb = (uint32_t)(ks * 32) + b_kh;

            uint32_t ah[2][4], al[2][4];
#pragma unroll
            for (int mt = 0; mt < 2; mt++) {
                uint32_t off = a_roff + (uint32_t)(mt * 16 * 128) + (akb ^ a_xor);
                LDM_X4(ah[mt], sAhi + off);
                LDM_X4(al[mt], sAlo + off);
            }
            uint32_t bh[4][4], bl[4][4];
#pragma unroll
            for (int bp = 0; bp < 4; bp++) {
                uint32_t n = (uint32_t)(bp * 16 + b_rsub);
                uint32_t off = n * 128 + (bkb ^ b_xor);
                LDM_X4(bh[bp], sBhi + off);
                LDM_X4(bl[bp], sBlo + off);
            }
#pragma unroll
            for (int mt = 0; mt < 2; mt++)
#pragma unroll
                for (int nt = 0; nt < 8; nt++) {
                    const int bp = nt >> 1, sel = (nt & 1) * 2;
                    MMA16816(acc[mt][nt], ah[mt], bh[bp][sel], bh[bp][sel + 1]);
                    MMA16816(acc[mt][nt], al[mt], bh[bp][sel], bh[bp][sel + 1]);
                    MMA16816(acc[mt][nt], ah[mt], bl[bp][sel], bl[bp][sel + 1]);
                }
        }
    }

    const int g  = lane >> 2;
    const int t4 = lane & 3;
#pragma unroll
    for (int mt = 0; mt < 2; mt++) {
        int r0 = vbase + m0 + mt * 16 + g;
        float bv0 = bih[r0] + bhh[r0];
        float bv8 = bih[r0 + 8] + bhh[r0 + 8];
#pragma unroll
        for (int nt = 0; nt < 8; nt++) {
            int t0 = nt * 8 + t4 * 2;
            g_Xg[xg_dst(r0,     t0)]     = acc[mt][nt][0] + bv0;
            g_Xg[xg_dst(r0,     t0 + 1)] = acc[mt][nt][1] + bv0;
            g_Xg[xg_dst(r0 + 8, t0)]     = acc[mt][nt][2] + bv8;
            g_Xg[xg_dst(r0 + 8, t0 + 1)] = acc[mt][nt][3] + bv8;
        }
    }
}

// =====================================================================
// K2: persistent LSTM recurrence (R11-proven) + L2 prefetch of fc_W.
// Quarter of threads issue ONE register-free prefetch.global.L2 per step
// (16384 lines/step x 64 steps = all 1.024M fc_W lines).
// =====================================================================
__global__ void __launch_bounds__(512, 1)
lstm_kernel(const float* __restrict__ Whh, const float* __restrict__ fcW) {
    __shared__ float partA[16][32];

    const int tid = threadIdx.x;
    const int w   = tid >> 5;
    const int l   = tid & 31;
    const int j   = tid & 7;
    const int c   = tid >> 3;
    const int b   = blockIdx.x;
    const int jg  = b * 8 + j;

    float creg = 0.f;

    unsigned long long wreg2[4][8];
#pragma unroll
    for (int g = 0; g < 4; g++) {
        const char* p = (const char*)(Whh + (size_t)(g * H_DIM + jg) * H_DIM + c * 16);
#pragma unroll
        for (int q = 0; q < 4; q++)
            ld2u64(p + q * 16, wreg2[g][2*q], wreg2[g][2*q+1]);
    }
    __syncthreads();

    for (int t = 0; t < T_STEPS; t++) {
        float xgv = 0.f;
        if (tid < 32)
            xgv = __ldcg(&g_Xg[t * NGATE + b * 32 + tid]);

        unsigned long long hv2[8];
        {
            const char* hp = (const char*)(g_hpub + t * H_DIM + c * 16);
#pragma unroll
            for (int q = 0; q < 4; q++)
                ld2u64_cg(hp + q * 16, hv2[2*q], hv2[2*q+1]);
        }

        // ---- fire-and-forget L2 prefetch of fc_W (no regs, no stores) ----
        if ((tid & 3) == 0) {
            unsigned int lineIdx = (unsigned)t * 16384u
                                 + (unsigned)(b * 128 + (tid >> 2));
            if (lineIdx < NWLINES) {
                const char* pf = (const char*)fcW + (size_t)lineIdx * 128;
                asm volatile("prefetch.global.L2 [%0];" :: "l"(pf));
            }
        }

        float part[4];
#pragma unroll
        for (int g = 0; g < 4; g++) {
            unsigned long long acc = 0ull;
#pragma unroll
            for (int i = 0; i < 8; i++) fma2(acc, wreg2[g][i], hv2[i]);
            part[g] = sum2(acc);
        }
#pragma unroll
        for (int g = 0; g < 4; g++) {
            part[g] += __shfl_xor_sync(0xffffffffu, part[g], 8);
            part[g] += __shfl_xor_sync(0xffffffffu, part[g], 16);
        }
        if (l < 8) {
#pragma unroll
            for (int g = 0; g < 4; g++) partA[w][g * 8 + l] = part[g];
        }
        __syncthreads();                          // sync1

        if (tid < 32) {
            float s = xgv;
#pragma unroll
            for (int ww = 0; ww < 16; ww++) s += partA[ww][tid];

            const int jj = tid & 7;
            float sf = __shfl_sync(0xffffffffu, s, jj + 8);
            float sg = __shfl_sync(0xffffffffu, s, jj + 16);
            float so = __shfl_sync(0xffffffffu, s, jj + 24);

            if (tid < 8) {
                float ii = sigmoidf_(s);
                float ff = sigmoidf_(sf);
                float gg = tanhf_(sg);
                float oo = sigmoidf_(so);
                float cc = ff * creg + ii * gg;
                creg = cc;
                float hn = oo * tanhf_(cc);
                g_hpub[(t + 1) * H_DIM + b * 8 + tid] = hn;
            }
            __syncwarp();
            if (tid == 0) {
                asm volatile("red.release.gpu.global.add.u32 [%0], 1;"
                             :: "l"(&g_cnt) : "memory");
            }
        } else if (tid == 32 && t + 1 < T_STEPS) {
            const unsigned int target = (unsigned)NBLK * (unsigned)(t + 1);
            unsigned int v;
            do {
                asm volatile("ld.acquire.gpu.u32 %0, [%1];"
                             : "=r"(v) : "l"(&g_cnt) : "memory");
            } while (v < target);
        }
        __syncthreads();                          // sync_final
    }
}

// =====================================================================
// K3: fc GEMM — fused-convert body (proven). fc_W now mostly L2-hot.
// =====================================================================
__global__ void __launch_bounds__(128, 2)
fc_mma_kernel(const float* __restrict__ fcW, const float* __restrict__ fcb,
              float* __restrict__ out) {
    extern __shared__ __align__(1024) char smem[];
    const uint32_t sb = smem_u32(smem);

    const int tid  = threadIdx.x;
    const int wid  = tid >> 5;
    const int lane = tid & 31;
    const int vbase = blockIdx.x * FC_M;
    const int m0 = wid * 32;

    const int a_row  = m0 + (lane & 15);
    const uint32_t a_roff = (uint32_t)a_row * 128;
    const uint32_t a_xor  = (uint32_t)(a_row & 7) << 4;
    const uint32_t a_kh   = (uint32_t)(lane >> 4) * 16;
    const int b_rsub = (lane & 7) + ((lane >> 4) & 1) * 8;
    const uint32_t b_xor = (uint32_t)(lane & 7) << 4;
    const uint32_t b_kh  = (uint32_t)((lane >> 3) & 1) * 16;

    float acc[2][8][4];
#pragma unroll
    for (int mt = 0; mt < 2; mt++)
#pragma unroll
        for (int nt = 0; nt < 8; nt++)
#pragma unroll
            for (int q = 0; q < 4; q++) acc[mt][nt][q] = 0.f;

    auto issue = [&](int c) {
        const uint32_t dbase = sb + FCO_AF32(c & 1);
#pragma unroll
        for (int p = 0; p < 16; p++) {
            int idx = tid + p * 128;
            int row = idx >> 4, seg = idx & 15;
            const char* src = (const char*)(fcW + (size_t)(vbase + row) * E_DIM + c * 64)
                              + seg * 16;
            CP16(dbase + (uint32_t)(row * 256 + seg * 16), src);
        }
        CP_COMMIT();
    };

    issue(0);
    issue(1);

    for (int c = 0; c < FC_NCH; c++) {
        if (c < FC_NCH - 1) { CP_WAIT(1); } else { CP_WAIT(0); }
        __syncthreads();

        {
            const char* af = smem + FCO_AF32(c & 1);
#pragma unroll
            for (int p = 0; p < 32; p++) {
                int fidx = tid + p * 128;
                int row = fidx >> 5, kp = fidx & 31;
                float2 a = *(const float2*)(af + row * 256 + kp * 8);
                uint32_t hi, lo; split2(a, hi, lo);
                uint32_t off = SWZ((uint32_t)(row * 128 + kp * 4));
                *(uint32_t*)(smem + FCO_AHI + off) = hi;
                *(uint32_t*)(smem + FCO_ALO + off) = lo;
            }
        }
        {
#pragma unroll
            for (int p = 0; p < 16; p++) {
                int fidx = tid + p * 128;
                int row = fidx >> 5, kp = fidx & 31;
                float2 a = *(const float2*)(g_hpub + (row + 1) * H_DIM + c * 64 + kp * 2);
                uint32_t hi, lo; split2(a, hi, lo);
                uint32_t off = SWZ((uint32_t)(row * 128 + kp * 4));
                *(uint32_t*)(smem + FCO_BHI + off) = hi;
                *(uint32_t*)(smem + FCO_BLO + off) = lo;
            }
        }
        __syncthreads();

        if (c + 2 < FC_NCH) issue(c + 2);

        const uint32_t sAhi = sb + FCO_AHI, sAlo = sb + FCO_ALO;
        const uint32_t sBhi = sb + FCO_BHI, sBlo = sb + FCO_BLO;
#pragma unroll
        for (int ks = 0; ks < 4; ks++) {
            const uint32_t akb = (uint32_t)(ks * 32) + a_kh;
            const uint32_t bkb = (uint32_t)(ks * 32) + b_kh;

            uint32_t ah[2][4], al[2][4];
#pragma unroll
            for (int mt = 0; mt < 2; mt++) {
                uint32_t off = a_roff + (uint32_t)(mt * 16 * 128) + (akb ^ a_xor);
                LDM_X4(ah[mt], sAhi + off);
                LDM_X4(al[mt], sAlo + off);
            }
            uint32_t bh[4][4], bl[4][4];
#pragma unroll
            for (int bp = 0; bp < 4; bp++) {
                uint32_t n = (uint32_t)(bp * 16 + b_rsub);
                uint32_t off = n * 128 + (bkb ^ b_xor);
                LDM_X4(bh[bp], sBhi + off);
                LDM_X4(bl[bp], sBlo + off);
            }
#pragma unroll
            for (int mt = 0; mt < 2; mt++)
#pragma unroll
                for (int nt = 0; nt < 8; nt++) {
                    const int bp = nt >> 1, sel = (nt & 1) * 2;
                    MMA16816(acc[mt][nt], ah[mt], bh[bp][sel], bh[bp][sel + 1]);
                    MMA16816(acc[mt][nt], al[mt], bh[bp][sel], bh[bp][sel + 1]);
                    MMA16816(acc[mt][nt], ah[mt], bl[bp][sel], bl[bp][sel + 1]);
                }
        }
    }

    const int g  = lane >> 2;
    const int t4 = lane & 3;
#pragma unroll
    for (int mt = 0; mt < 2; mt++) {
        int v0 = vbase + m0 + mt * 16 + g;
        float bv0 = fcb[v0];
        float bv8 = fcb[v0 + 8];
#pragma unroll
        for (int nt = 0; nt < 8; nt++) {
            int t0 = nt * 8 + t4 * 2;
            out[(size_t)t0 * VOC + v0]           = acc[mt][nt][0] + bv0;
            out[(size_t)(t0 + 1) * VOC + v0]     = acc[mt][nt][1] + bv0;
            out[(size_t)t0 * VOC + v0 + 8]       = acc[mt][nt][2] + bv8;
            out[(size_t)(t0 + 1) * VOC + v0 + 8] = acc[mt][nt][3] + bv8;
        }
    }
}

// =====================================================================
// launch
// =====================================================================
extern "C" void kernel_launch(void* const* d_in, const int* in_sizes, int n_in,
                              void* d_out, int out_size) {
    const int*   captions = (const int*)  d_in[0];
    const float* features = (const float*)d_in[1];
    const float* etab     = (const float*)d_in[2];
    const float* W_ih     = (const float*)d_in[3];
    const float* W_hh     = (const float*)d_in[4];
    const float* b_ih     = (const float*)d_in[5];
    const float* b_hh     = (const float*)d_in[6];
    const float* fc_W     = (const float*)d_in[7];
    const float* fc_b     = (const float*)d_in[8];
    float* out = (float*)d_out;

    cudaFuncSetAttribute(xg_mma_kernel,
                         cudaFuncAttributeMaxDynamicSharedMemorySize, FC_SMEM);
    cudaFuncSetAttribute(fc_mma_kernel,
                         cudaFuncAttributeMaxDynamicSharedMemorySize, FC_SMEM);

    prep_kernel<<<T_STEPS, 256>>>(captions, features, etab);
    xg_mma_kernel<<<NGATE / FC_M, 128, FC_SMEM>>>(W_ih, b_ih, b_hh);
    lstm_kernel<<<NBLK, 512>>>(W_hh, fc_W);
    fc_mma_kernel<<<VOC / FC_M, 128, FC_SMEM>>>(fc_W, fc_b, out);
}

// round 14
// speedup vs baseline: 1.4551x; 1.0298x over previous
#include <cuda_runtime.h>
#include <cuda_bf16.h>
#include <cstdint>
#include <cstdio>

#define E_DIM 1024
#define H_DIM 1024
#define VOC   32000
#define T_STEPS 64
#define NBLK  128
#define NGATE 4096

// -------- device scratch --------
__device__ float g_X[T_STEPS * E_DIM];
__device__ float g_hpub[(T_STEPS + 1) * H_DIM];
__device__ float g_Xg[T_STEPS * NGATE];
__device__ unsigned int g_cnt;
// hs pre-split to bf16 hi/lo, pre-swizzled (lstm tail), R12-proven layout
__device__ __nv_bfloat16 g_Bhi[T_STEPS * H_DIM];
__device__ __nv_bfloat16 g_Blo[T_STEPS * H_DIM];

__device__ __forceinline__ float sigmoidf_(float x) { return 1.f / (1.f + __expf(-x)); }
__device__ __forceinline__ float tanhf_(float x) {
    return __fdividef(2.f, 1.f + __expf(-2.f * x)) - 1.f;
}

// ---- packed f32x2 helpers ----
__device__ __forceinline__ void fma2(unsigned long long& d,
                                     unsigned long long a, unsigned long long b) {
    asm("fma.rn.f32x2 %0, %1, %2, %0;" : "+l"(d) : "l"(a), "l"(b));
}
__device__ __forceinline__ float sum2(unsigned long long v) {
    float lo, hi;
    asm("mov.b64 {%0, %1}, %2;" : "=f"(lo), "=f"(hi) : "l"(v));
    return lo + hi;
}
__device__ __forceinline__ void ld2u64(const void* p, unsigned long long& a,
                                       unsigned long long& b) {
    asm("ld.global.v2.u64 {%0, %1}, [%2];" : "=l"(a), "=l"(b) : "l"(p));
}
__device__ __forceinline__ void ld2u64_cg(const void* p, unsigned long long& a,
                                          unsigned long long& b) {
    asm("ld.global.cg.v2.u64 {%0, %1}, [%2];" : "=l"(a), "=l"(b) : "l"(p));
}

// =====================================================================
// K0: build X, init h row 0 + counter
// =====================================================================
__global__ void prep_kernel(const int* __restrict__ captions,
                            const float* __restrict__ features,
                            const float* __restrict__ etab) {
    int t = blockIdx.x;
    const float* src = (t == 0) ? features : (etab + (size_t)captions[t - 1] * E_DIM);
    for (int k = threadIdx.x; k < E_DIM; k += blockDim.x)
        g_X[t * E_DIM + k] = src[k];
    if (t == 0) {
        for (int k = threadIdx.x; k < H_DIM; k += blockDim.x) g_hpub[k] = 0.f;
        if (threadIdx.x == 0) g_cnt = 0u;
    }
}

// ======================= shared GEMM helpers =========================
#define FC_M    128
#define FC_NCH  16
#define SWZ(x) ((x) ^ (((x) >> 3) & 0x70))

__device__ __forceinline__ uint32_t smem_u32(const void* p) {
    uint32_t a;
    asm("{ .reg .u64 t; cvta.to.shared.u64 t, %1; cvt.u32.u64 %0, t; }" : "=r"(a) : "l"(p));
    return a;
}

__device__ __forceinline__ void split2(float2 a, uint32_t& hi, uint32_t& lo) {
    __nv_bfloat162 h = __float22bfloat162_rn(a);
    float2 f = __bfloat1622float2(h);
    __nv_bfloat162 l2 = __float22bfloat162_rn(make_float2(a.x - f.x, a.y - f.y));
    hi = *reinterpret_cast<uint32_t*>(&h);
    lo = *reinterpret_cast<uint32_t*>(&l2);
}

#define CP16(dst, src) \
    asm volatile("cp.async.cg.shared.global [%0], [%1], 16;" :: "r"(dst), "l"(src) : "memory")
#define CP_COMMIT() asm volatile("cp.async.commit_group;" ::: "memory")
#define CP_WAIT(n)  asm volatile("cp.async.wait_group %0;" :: "n"(n) : "memory")

#define LDM_X4(r, a)                                                          \
    asm volatile("ldmatrix.sync.aligned.m8n8.x4.shared.b16 {%0,%1,%2,%3}, [%4];" \
        : "=r"((r)[0]), "=r"((r)[1]), "=r"((r)[2]), "=r"((r)[3]) : "r"(a))

#define MMA16816(d, a, b0, b1)                                                \
    asm volatile("mma.sync.aligned.m16n8k16.row.col.f32.bf16.bf16.f32 "       \
        "{%0,%1,%2,%3},{%4,%5,%6,%7},{%8,%9},{%0,%1,%2,%3};"                  \
        : "+f"((d)[0]), "+f"((d)[1]), "+f"((d)[2]), "+f"((d)[3])              \
        : "r"((a)[0]), "r"((a)[1]), "r"((a)[2]), "r"((a)[3]),                 \
          "r"(b0), "r"(b1))

// =====================================================================
// K1: Xg = X @ W_ih^T + bias (32 CTAs) — proven fused-convert body.
// =====================================================================
#define XGO_AF32(b) ((b) * 32768)
#define XGO_AHI     65536
#define XGO_ALO     81920
#define XGO_BHI     98304
#define XGO_BLO     106496
#define XG_SMEM     114688

__device__ __forceinline__ int xg_dst(int r, int t) {
    return t * NGATE + (((r & 1023) >> 3) << 5) + ((r >> 10) << 3) + (r & 7);
}

__global__ void __launch_bounds__(128, 2)
xg_mma_kernel(const float* __restrict__ Wih,
              const float* __restrict__ bih, const float* __restrict__ bhh) {
    extern __shared__ __align__(1024) char smem[];
    const uint32_t sb = smem_u32(smem);

    const int tid  = threadIdx.x;
    const int wid  = tid >> 5;
    const int lane = tid & 31;
    const int vbase = blockIdx.x * FC_M;
    const int m0 = wid * 32;

    const int a_row  = m0 + (lane & 15);
    const uint32_t a_roff = (uint32_t)a_row * 128;
    const uint32_t a_xor  = (uint32_t)(a_row & 7) << 4;
    const uint32_t a_kh   = (uint32_t)(lane >> 4) * 16;
    const int b_rsub = (lane & 7) + ((lane >> 4) & 1) * 8;
    const uint32_t b_xor = (uint32_t)(lane & 7) << 4;
    const uint32_t b_kh  = (uint32_t)((lane >> 3) & 1) * 16;

    float acc[2][8][4];
#pragma unroll
    for (int mt = 0; mt < 2; mt++)
#pragma unroll
        for (int nt = 0; nt < 8; nt++)
#pragma unroll
            for (int q = 0; q < 4; q++) acc[mt][nt][q] = 0.f;

    auto issue = [&](int c) {
        const uint32_t dbase = sb + XGO_AF32(c & 1);
#pragma unroll
        for (int p = 0; p < 16; p++) {
            int idx = tid + p * 128;
            int row = idx >> 4, seg = idx & 15;
            const char* src = (const char*)(Wih + (size_t)(vbase + row) * E_DIM + c * 64)
                              + seg * 16;
            CP16(dbase + (uint32_t)(row * 256 + seg * 16), src);
        }
        CP_COMMIT();
    };

    issue(0);
    issue(1);

    for (int c = 0; c < FC_NCH; c++) {
        if (c < FC_NCH - 1) { CP_WAIT(1); } else { CP_WAIT(0); }
        __syncthreads();

        {
            const char* af = smem + XGO_AF32(c & 1);
#pragma unroll
            for (int p = 0; p < 32; p++) {
                int fidx = tid + p * 128;
                int row = fidx >> 5, kp = fidx & 31;
                float2 a = *(const float2*)(af + row * 256 + kp * 8);
                uint32_t hi, lo; split2(a, hi, lo);
                uint32_t off = SWZ((uint32_t)(row * 128 + kp * 4));
                *(uint32_t*)(smem + XGO_AHI + off) = hi;
                *(uint32_t*)(smem + XGO_ALO + off) = lo;
            }
        }
        {
#pragma unroll
            for (int p = 0; p < 16; p++) {
                int fidx = tid + p * 128;
                int row = fidx >> 5, kp = fidx & 31;
                float2 a = *(const float2*)(g_X + row * E_DIM + c * 64 + kp * 2);
                uint32_t hi, lo; split2(a, hi, lo);
                uint32_t off = SWZ((uint32_t)(row * 128 + kp * 4));
                *(uint32_t*)(smem + XGO_BHI + off) = hi;
                *(uint32_t*)(smem + XGO_BLO + off) = lo;
            }
        }
        __syncthreads();

        if (c + 2 < FC_NCH) issue(c + 2);

        const uint32_t sAhi = sb + XGO_AHI, sAlo = sb + XGO_ALO;
        const uint32_t sBhi = sb + XGO_BHI, sBlo = sb + XGO_BLO;
#pragma unroll
        for (int ks = 0; ks < 4; ks++) {
            const uint32_t akb = (uint32_t)(ks * 32) + a_kh;
            const uint32_t bkb = (uint32_t)(ks * 32) + b_kh;

            uint32_t ah[2][4], al[2][4];
#pragma unroll
            for (int mt = 0; mt < 2; mt++) {
                uint32_t off = a_roff + (uint32_t)(mt * 16 * 128) + (akb ^ a_xor);
                LDM_X4(ah[mt], sAhi + off);
                LDM_X4(al[mt], sAlo + off);
            }
            uint32_t bh[4][4], bl[4][4];
#pragma unroll
            for (int bp = 0; bp < 4; bp++) {
                uint32_t n = (uint32_t)(bp * 16 + b_rsub);
                uint32_t off = n * 128 + (bkb ^ b_xor);
                LDM_X4(bh[bp], sBhi + off);
                LDM_X4(bl[bp], sBlo + off);
            }
#pragma unroll
            for (int mt = 0; mt < 2; mt++)
#pragma unroll
                for (int nt = 0; nt < 8; nt++) {
                    const int bp = nt >> 1, sel = (nt & 1) * 2;
                    MMA16816(acc[mt][nt], ah[mt], bh[bp][sel], bh[bp][sel + 1]);
                    MMA16816(acc[mt][nt], al[mt], bh[bp][sel], bh[bp][sel + 1]);
                    MMA16816(acc[mt][nt], ah[mt], bl[bp][sel], bl[bp][sel + 1]);
                }
        }
    }

    const int g  = lane >> 2;
    const int t4 = lane & 3;
#pragma unroll
    for (int mt = 0; mt < 2; mt++) {
        int r0 = vbase + m0 + mt * 16 + g;
        float bv0 = bih[r0] + bhh[r0];
        float bv8 = bih[r0 + 8] + bhh[r0 + 8];
#pragma unroll
        for (int nt = 0; nt < 8; nt++) {
            int t0 = nt * 8 + t4 * 2;
            g_Xg[xg_dst(r0,     t0)]     = acc[mt][nt][0] + bv0;
            g_Xg[xg_dst(r0,     t0 + 1)] = acc[mt][nt][1] + bv0;
            g_Xg[xg_dst(r0 + 8, t0)]     = acc[mt][nt][2] + bv8;
            g_Xg[xg_dst(r0 + 8, t0 + 1)] = acc[mt][nt][3] + bv8;
        }
    }
}

// =====================================================================
// K2: persistent LSTM recurrence (R11-proven, prefetch removed).
// Tail: one-shot hs -> g_Bhi/g_Blo split (pre-swizzled).
// =====================================================================
__global__ void __launch_bounds__(512, 1)
lstm_kernel(const float* __restrict__ Whh) {
    __shared__ float partA[16][32];

    const int tid = threadIdx.x;
    const int w   = tid >> 5;
    const int l   = tid & 31;
    const int j   = tid & 7;
    const int c   = tid >> 3;
    const int b   = blockIdx.x;
    const int jg  = b * 8 + j;

    float creg = 0.f;

    unsigned long long wreg2[4][8];
#pragma unroll
    for (int g = 0; g < 4; g++) {
        const char* p = (const char*)(Whh + (size_t)(g * H_DIM + jg) * H_DIM + c * 16);
#pragma unroll
        for (int q = 0; q < 4; q++)
            ld2u64(p + q * 16, wreg2[g][2*q], wreg2[g][2*q+1]);
    }
    __syncthreads();

    for (int t = 0; t < T_STEPS; t++) {
        float xgv = 0.f;
        if (tid < 32)
            xgv = __ldcg(&g_Xg[t * NGATE + b * 32 + tid]);

        unsigned long long hv2[8];
        {
            const char* hp = (const char*)(g_hpub + t * H_DIM + c * 16);
#pragma unroll
            for (int q = 0; q < 4; q++)
                ld2u64_cg(hp + q * 16, hv2[2*q], hv2[2*q+1]);
        }
        float part[4];
#pragma unroll
        for (int g = 0; g < 4; g++) {
            unsigned long long acc = 0ull;
#pragma unroll
            for (int i = 0; i < 8; i++) fma2(acc, wreg2[g][i], hv2[i]);
            part[g] = sum2(acc);
        }
#pragma unroll
        for (int g = 0; g < 4; g++) {
            part[g] += __shfl_xor_sync(0xffffffffu, part[g], 8);
            part[g] += __shfl_xor_sync(0xffffffffu, part[g], 16);
        }
        if (l < 8) {
#pragma unroll
            for (int g = 0; g < 4; g++) partA[w][g * 8 + l] = part[g];
        }
        __syncthreads();                          // sync1

        if (tid < 32) {
            float s = xgv;
#pragma unroll
            for (int ww = 0; ww < 16; ww++) s += partA[ww][tid];

            const int jj = tid & 7;
            float sf = __shfl_sync(0xffffffffu, s, jj + 8);
            float sg = __shfl_sync(0xffffffffu, s, jj + 16);
            float so = __shfl_sync(0xffffffffu, s, jj + 24);

            if (tid < 8) {
                float ii = sigmoidf_(s);
                float ff = sigmoidf_(sf);
                float gg = tanhf_(sg);
                float oo = sigmoidf_(so);
                float cc = ff * creg + ii * gg;
                creg = cc;
                float hn = oo * tanhf_(cc);
                g_hpub[(t + 1) * H_DIM + b * 8 + tid] = hn;
            }
            __syncwarp();
            if (tid == 0) {
                asm volatile("red.release.gpu.global.add.u32 [%0], 1;"
                             :: "l"(&g_cnt) : "memory");
            }
        } else if (tid == 32) {
            // poll every step (tail below needs ALL h rows, incl. t=63)
            const unsigned int target = (unsigned)NBLK * (unsigned)(t + 1);
            unsigned int v;
            do {
                asm volatile("ld.acquire.gpu.u32 %0, [%1];"
                             : "=r"(v) : "l"(&g_cnt) : "memory");
            } while (v < target);
        }
        __syncthreads();                          // sync_final
    }

    // ---- tail: split hs rows (g_hpub 1..64) -> g_Bhi/g_Blo, pre-swizzled ----
    {
        int idx = b * 512 + tid;          // 0..65535
        int t = idx >> 10;
        int e = idx & 1023;
        int cc2 = e >> 6, ee = e & 63;
        float v = __ldcg(&g_hpub[(t + 1) * H_DIM + e]);
        __nv_bfloat16 hb = __float2bfloat16(v);
        float hf = __bfloat162float(hb);
        __nv_bfloat16 lb = __float2bfloat16(v - hf);
        size_t dst = ((size_t)t * 16 + cc2) * 64 + (((ee >> 3) ^ (t & 7)) << 3) + (ee & 7);
        g_Bhi[dst] = hb;
        g_Blo[dst] = lb;
    }
}

// =====================================================================
// K3: fc GEMM — A fused-convert (single f32 buffer), B pure cp.async of
// pre-split bf16 (double-buffered). 96KB smem.
// =====================================================================
#define FO_AF32   0                              // 32KB
#define FO_AHI    32768                          // 16KB
#define FO_ALO    49152                          // 16KB
#define FO_BHI(b) (65536 + (b) * 16384)          // 8KB each
#define FO_BLO(b) (65536 + (b) * 16384 + 8192)
#define FC_SMEM2  98304                          // 96KB -> 2 CTAs/SM

__global__ void __launch_bounds__(128, 2)
fc_mma_kernel(const float* __restrict__ fcW, const float* __restrict__ fcb,
              float* __restrict__ out) {
    extern __shared__ __align__(1024) char smem[];
    const uint32_t sb = smem_u32(smem);

    const int tid  = threadIdx.x;
    const int wid  = tid >> 5;
    const int lane = tid & 31;
    const int vbase = blockIdx.x * FC_M;
    const int m0 = wid * 32;

    const int a_row  = m0 + (lane & 15);
    const uint32_t a_roff = (uint32_t)a_row * 128;
    const uint32_t a_xor  = (uint32_t)(a_row & 7) << 4;
    const uint32_t a_kh   = (uint32_t)(lane >> 4) * 16;
    const int b_rsub = (lane & 7) + ((lane >> 4) & 1) * 8;
    const uint32_t b_xor = (uint32_t)(lane & 7) << 4;
    const uint32_t b_kh  = (uint32_t)((lane >> 3) & 1) * 16;

    float acc[2][8][4];
#pragma unroll
    for (int mt = 0; mt < 2; mt++)
#pragma unroll
        for (int nt = 0; nt < 8; nt++)
#pragma unroll
            for (int q = 0; q < 4; q++) acc[mt][nt][q] = 0.f;

    // issue A(c) f32 + B(c) bf16 as ONE commit group
    auto issueAB = [&](int c) {
#pragma unroll
        for (int p = 0; p < 16; p++) {           // A: 2048 x 16B fp32
            int idx = tid + p * 128;
            int row = idx >> 4, seg = idx & 15;
            const char* src = (const char*)(fcW + (size_t)(vbase + row) * E_DIM + c * 64)
                              + seg * 16;
            CP16(sb + FO_AF32 + (uint32_t)(row * 256 + seg * 16), src);
        }
        const int buf = c & 1;
#pragma unroll
        for (int p = 0; p < 8; p++) {            // B: 1024 x 16B bf16 (hi+lo)
            int idx = tid + p * 128;
            int hl  = idx >> 9;
            int row = (idx >> 3) & 63;
            int seg = idx & 7;
            const char* src = (const char*)(hl ? g_Blo : g_Bhi)
                + (((size_t)row * 16 + c) * 128 + seg * 16);
            uint32_t dst = sb + (hl ? FO_BLO(buf) : FO_BHI(buf)) + row * 128 + seg * 16;
            CP16(dst, src);
        }
        CP_COMMIT();
    };

    issueAB(0);

    for (int c = 0; c < FC_NCH; c++) {
        CP_WAIT(0);
        __syncthreads();   // A(c) f32 + B(c) bf16 landed; prev MMA done

        // ---- convert A: f32 smem -> bf16 hi/lo smem (SW128) ----
        {
            const char* af = smem + FO_AF32;
#pragma unroll
            for (int p = 0; p < 32; p++) {
                int fidx = tid + p * 128;
                int row = fidx >> 5, kp = fidx & 31;
                float2 a = *(const float2*)(af + row * 256 + kp * 8);
                uint32_t hi, lo; split2(a, hi, lo);
                uint32_t off = SWZ((uint32_t)(row * 128 + kp * 4));
                *(uint32_t*)(smem + FO_AHI + off) = hi;
                *(uint32_t*)(smem + FO_ALO + off) = lo;
            }
        }
        __syncthreads();   // ABF ready, AF32 free

        if (c + 1 < FC_NCH) issueAB(c + 1);

        const uint32_t sAhi = sb + FO_AHI, sAlo = sb + FO_ALO;
        const uint32_t sBhi = sb + FO_BHI(c & 1), sBlo = sb + FO_BLO(c & 1);
#pragma unroll
        for (int ks = 0; ks < 4; ks++) {
            const uint32_t akb = (uint32_t)(ks * 32) + a_kh;
            const uint32_t bkb = (uint32_t)(ks * 32) + b_kh;

            uint32_t ah[2][4], al[2][4];
#pragma unroll
            for (int mt = 0; mt < 2; mt++) {
                uint32_t off = a_roff + (uint32_t)(mt * 16 * 128) + (akb ^ a_xor);
                LDM_X4(ah[mt], sAhi + off);
                LDM_X4(al[mt], sAlo + off);
            }
            uint32_t bh[4][4], bl[4][4];
#pragma unroll
            for (int bp = 0; bp < 4; bp++) {
                uint32_t n = (uint32_t)(bp * 16 + b_rsub);
                uint32_t off = n * 128 + (bkb ^ b_xor);
                LDM_X4(bh[bp], sBhi + off);
                LDM_X4(bl[bp], sBlo + off);
            }
#pragma unroll
            for (int mt = 0; mt < 2; mt++)
#pragma unroll
                for (int nt = 0; nt < 8; nt++) {
                    const int bp = nt >> 1, sel = (nt & 1) * 2;
                    MMA16816(acc[mt][nt], ah[mt], bh[bp][sel], bh[bp][sel + 1]);
                    MMA16816(acc[mt][nt], al[mt], bh[bp][sel], bh[bp][sel + 1]);
                    MMA16816(acc[mt][nt], ah[mt], bl[bp][sel], bl[bp][sel + 1]);
                }
        }
    }

    const int g  = lane >> 2;
    const int t4 = lane & 3;
#pragma unroll
    for (int mt = 0; mt < 2; mt++) {
        int v0 = vbase + m0 + mt * 16 + g;
        float bv0 = fcb[v0];
        float bv8 = fcb[v0 + 8];
#pragma unroll
        for (int nt = 0; nt < 8; nt++) {
            int t0 = nt * 8 + t4 * 2;
            out[(size_t)t0 * VOC + v0]           = acc[mt][nt][0] + bv0;
            out[(size_t)(t0 + 1) * VOC + v0]     = acc[mt][nt][1] + bv0;
            out[(size_t)t0 * VOC + v0 + 8]       = acc[mt][nt][2] + bv8;
            out[(size_t)(t0 + 1) * VOC + v0 + 8] = acc[mt][nt][3] + bv8;
        }
    }
}

// =====================================================================
// launch
// =====================================================================
extern "C" void kernel_launch(void* const* d_in, const int* in_sizes, int n_in,
                              void* d_out, int out_size) {
    const int*   captions = (const int*)  d_in[0];
    const float* features = (const float*)d_in[1];
    const float* etab     = (const float*)d_in[2];
    const float* W_ih     = (const float*)d_in[3];
    const float* W_hh     = (const float*)d_in[4];
    const float* b_ih     = (const float*)d_in[5];
    const float* b_hh     = (const float*)d_in[6];
    const float* fc_W     = (const float*)d_in[7];
    const float* fc_b     = (const float*)d_in[8];
    float* out = (float*)d_out;

    cudaFuncSetAttribute(xg_mma_kernel,
                         cudaFuncAttributeMaxDynamicSharedMemorySize, XG_SMEM);
    cudaFuncSetAttribute(fc_mma_kernel,
                         cudaFuncAttributeMaxDynamicSharedMemorySize, FC_SMEM2);

    prep_kernel<<<T_STEPS, 256>>>(captions, features, etab);
    xg_mma_kernel<<<NGATE / FC_M, 128, XG_SMEM>>>(W_ih, b_ih, b_hh);
    lstm_kernel<<<NBLK, 512>>>(W_hh);
    fc_mma_kernel<<<VOC / FC_M, 128, FC_SMEM2>>>(fc_W, fc_b, out);
}

// round 15
// speedup vs baseline: 1.4653x; 1.0070x over previous
#include <cuda_runtime.h>
#include <cuda_bf16.h>
#include <cstdint>
#include <cstdio>

#define E_DIM 1024
#define H_DIM 1024
#define VOC   32000
#define T_STEPS 64
#define NBLK  128
#define NGATE 4096

// -------- device scratch --------
__device__ float g_X[T_STEPS * E_DIM];
__device__ float g_hpub[(T_STEPS + 1) * H_DIM];
__device__ float g_Xg[T_STEPS * NGATE];
__device__ unsigned int g_cnt;
// hs pre-split to bf16 hi/lo, pre-swizzled (lstm tail)
__device__ __nv_bfloat16 g_Bhi[T_STEPS * H_DIM];
__device__ __nv_bfloat16 g_Blo[T_STEPS * H_DIM];

__device__ __forceinline__ float sigmoidf_(float x) { return 1.f / (1.f + __expf(-x)); }
__device__ __forceinline__ float tanhf_(float x) {
    return __fdividef(2.f, 1.f + __expf(-2.f * x)) - 1.f;
}

// ---- packed f32x2 helpers ----
__device__ __forceinline__ void fma2(unsigned long long& d,
                                     unsigned long long a, unsigned long long b) {
    asm("fma.rn.f32x2 %0, %1, %2, %0;" : "+l"(d) : "l"(a), "l"(b));
}
__device__ __forceinline__ float sum2(unsigned long long v) {
    float lo, hi;
    asm("mov.b64 {%0, %1}, %2;" : "=f"(lo), "=f"(hi) : "l"(v));
    return lo + hi;
}
__device__ __forceinline__ void ld2u64(const void* p, unsigned long long& a,
                                       unsigned long long& b) {
    asm("ld.global.v2.u64 {%0, %1}, [%2];" : "=l"(a), "=l"(b) : "l"(p));
}
__device__ __forceinline__ void ld2u64_cg(const void* p, unsigned long long& a,
                                          unsigned long long& b) {
    asm("ld.global.cg.v2.u64 {%0, %1}, [%2];" : "=l"(a), "=l"(b) : "l"(p));
}

// =====================================================================
// K0: build X, init h row 0 + counter
// =====================================================================
__global__ void prep_kernel(const int* __restrict__ captions,
                            const float* __restrict__ features,
                            const float* __restrict__ etab) {
    int t = blockIdx.x;
    const float* src = (t == 0) ? features : (etab + (size_t)captions[t - 1] * E_DIM);
    for (int k = threadIdx.x; k < E_DIM; k += blockDim.x)
        g_X[t * E_DIM + k] = src[k];
    if (t == 0) {
        for (int k = threadIdx.x; k < H_DIM; k += blockDim.x) g_hpub[k] = 0.f;
        if (threadIdx.x == 0) g_cnt = 0u;
    }
}

// ======================= shared GEMM helpers =========================
#define FC_M    128
#define FC_NCH  16
#define SWZ(x) ((x) ^ (((x) >> 3) & 0x70))

__device__ __forceinline__ uint32_t smem_u32(const void* p) {
    uint32_t a;
    asm("{ .reg .u64 t; cvta.to.shared.u64 t, %1; cvt.u32.u64 %0, t; }" : "=r"(a) : "l"(p));
    return a;
}

__device__ __forceinline__ void split2(float2 a, uint32_t& hi, uint32_t& lo) {
    __nv_bfloat162 h = __float22bfloat162_rn(a);
    float2 f = __bfloat1622float2(h);
    __nv_bfloat162 l2 = __float22bfloat162_rn(make_float2(a.x - f.x, a.y - f.y));
    hi = *reinterpret_cast<uint32_t*>(&h);
    lo = *reinterpret_cast<uint32_t*>(&l2);
}

#define CP16(dst, src) \
    asm volatile("cp.async.cg.shared.global [%0], [%1], 16;" :: "r"(dst), "l"(src) : "memory")
#define CP_COMMIT() asm volatile("cp.async.commit_group;" ::: "memory")
#define CP_WAIT(n)  asm volatile("cp.async.wait_group %0;" :: "n"(n) : "memory")

#define LDM_X4(r, a)                                                          \
    asm volatile("ldmatrix.sync.aligned.m8n8.x4.shared.b16 {%0,%1,%2,%3}, [%4];" \
        : "=r"((r)[0]), "=r"((r)[1]), "=r"((r)[2]), "=r"((r)[3]) : "r"(a))

#define MMA16816(d, a, b0, b1)                                                \
    asm volatile("mma.sync.aligned.m16n8k16.row.col.f32.bf16.bf16.f32 "       \
        "{%0,%1,%2,%3},{%4,%5,%6,%7},{%8,%9},{%0,%1,%2,%3};"                  \
        : "+f"((d)[0]), "+f"((d)[1]), "+f"((d)[2]), "+f"((d)[3])              \
        : "r"((a)[0]), "r"((a)[1]), "r"((a)[2]), "r"((a)[3]),                 \
          "r"(b0), "r"(b1))

// =====================================================================
// K1: Xg = X @ W_ih^T + bias (32 CTAs) — proven fused-convert body,
// with the low-register-pressure per-bp B loading.
// =====================================================================
#define XGO_AF32(b) ((b) * 32768)
#define XGO_AHI     65536
#define XGO_ALO     81920
#define XGO_BHI     98304
#define XGO_BLO     106496
#define XG_SMEM     114688

__device__ __forceinline__ int xg_dst(int r, int t) {
    return t * NGATE + (((r & 1023) >> 3) << 5) + ((r >> 10) << 3) + (r & 7);
}

__global__ void __launch_bounds__(128, 2)
xg_mma_kernel(const float* __restrict__ Wih,
              const float* __restrict__ bih, const float* __restrict__ bhh) {
    extern __shared__ __align__(1024) char smem[];
    const uint32_t sb = smem_u32(smem);

    const int tid  = threadIdx.x;
    const int wid  = tid >> 5;
    const int lane = tid & 31;
    const int vbase = blockIdx.x * FC_M;
    const int m0 = wid * 32;

    const int a_row  = m0 + (lane & 15);
    const uint32_t a_roff = (uint32_t)a_row * 128;
    const uint32_t a_xor  = (uint32_t)(a_row & 7) << 4;
    const uint32_t a_kh   = (uint32_t)(lane >> 4) * 16;
    const int b_rsub = (lane & 7) + ((lane >> 4) & 1) * 8;
    const uint32_t b_xor = (uint32_t)(lane & 7) << 4;
    const uint32_t b_kh  = (uint32_t)((lane >> 3) & 1) * 16;

    float acc[2][8][4];
#pragma unroll
    for (int mt = 0; mt < 2; mt++)
#pragma unroll
        for (int nt = 0; nt < 8; nt++)
#pragma unroll
            for (int q = 0; q < 4; q++) acc[mt][nt][q] = 0.f;

    auto issue = [&](int c) {
        const uint32_t dbase = sb + XGO_AF32(c & 1);
#pragma unroll
        for (int p = 0; p < 16; p++) {
            int idx = tid + p * 128;
            int row = idx >> 4, seg = idx & 15;
            const char* src = (const char*)(Wih + (size_t)(vbase + row) * E_DIM + c * 64)
                              + seg * 16;
            CP16(dbase + (uint32_t)(row * 256 + seg * 16), src);
        }
        CP_COMMIT();
    };

    issue(0);
    issue(1);

    for (int c = 0; c < FC_NCH; c++) {
        if (c < FC_NCH - 1) { CP_WAIT(1); } else { CP_WAIT(0); }
        __syncthreads();

        {
            const char* af = smem + XGO_AF32(c & 1);
#pragma unroll
            for (int p = 0; p < 32; p++) {
                int fidx = tid + p * 128;
                int row = fidx >> 5, kp = fidx & 31;
                float2 a = *(const float2*)(af + row * 256 + kp * 8);
                uint32_t hi, lo; split2(a, hi, lo);
                uint32_t off = SWZ((uint32_t)(row * 128 + kp * 4));
                *(uint32_t*)(smem + XGO_AHI + off) = hi;
                *(uint32_t*)(smem + XGO_ALO + off) = lo;
            }
        }
        {
#pragma unroll
            for (int p = 0; p < 16; p++) {
                int fidx = tid + p * 128;
                int row = fidx >> 5, kp = fidx & 31;
                float2 a = *(const float2*)(g_X + row * E_DIM + c * 64 + kp * 2);
                uint32_t hi, lo; split2(a, hi, lo);
                uint32_t off = SWZ((uint32_t)(row * 128 + kp * 4));
                *(uint32_t*)(smem + XGO_BHI + off) = hi;
                *(uint32_t*)(smem + XGO_BLO + off) = lo;
            }
        }
        __syncthreads();

        if (c + 2 < FC_NCH) issue(c + 2);

        const uint32_t sAhi = sb + XGO_AHI, sAlo = sb + XGO_ALO;
        const uint32_t sBhi = sb + XGO_BHI, sBlo = sb + XGO_BLO;
#pragma unroll
        for (int ks = 0; ks < 4; ks++) {
            const uint32_t akb = (uint32_t)(ks * 32) + a_kh;
            const uint32_t bkb = (uint32_t)(ks * 32) + b_kh;

            uint32_t ah[2][4], al[2][4];
#pragma unroll
            for (int mt = 0; mt < 2; mt++) {
                uint32_t off = a_roff + (uint32_t)(mt * 16 * 128) + (akb ^ a_xor);
                LDM_X4(ah[mt], sAhi + off);
                LDM_X4(al[mt], sAlo + off);
            }
#pragma unroll
            for (int bp = 0; bp < 4; bp++) {
                uint32_t n = (uint32_t)(bp * 16 + b_rsub);
                uint32_t off = n * 128 + (bkb ^ b_xor);
                uint32_t bh[4], bl[4];
                LDM_X4(bh, sBhi + off);
                LDM_X4(bl, sBlo + off);
#pragma unroll
                for (int mt = 0; mt < 2; mt++)
#pragma unroll
                    for (int sub = 0; sub < 2; sub++) {
                        const int nt = bp * 2 + sub, sel = sub * 2;
                        MMA16816(acc[mt][nt], ah[mt], bh[sel], bh[sel + 1]);
                        MMA16816(acc[mt][nt], al[mt], bh[sel], bh[sel + 1]);
                        MMA16816(acc[mt][nt], ah[mt], bl[sel], bl[sel + 1]);
                    }
            }
        }
    }

    const int g  = lane >> 2;
    const int t4 = lane & 3;
#pragma unroll
    for (int mt = 0; mt < 2; mt++) {
        int r0 = vbase + m0 + mt * 16 + g;
        float bv0 = bih[r0] + bhh[r0];
        float bv8 = bih[r0 + 8] + bhh[r0 + 8];
#pragma unroll
        for (int nt = 0; nt < 8; nt++) {
            int t0 = nt * 8 + t4 * 2;
            g_Xg[xg_dst(r0,     t0)]     = acc[mt][nt][0] + bv0;
            g_Xg[xg_dst(r0,     t0 + 1)] = acc[mt][nt][1] + bv0;
            g_Xg[xg_dst(r0 + 8, t0)]     = acc[mt][nt][2] + bv8;
            g_Xg[xg_dst(r0 + 8, t0 + 1)] = acc[mt][nt][3] + bv8;
        }
    }
}

// =====================================================================
// K2: persistent LSTM recurrence (R14 skeleton; relaxed poll + single
// acquire after detection). Tail: one-shot hs -> g_Bhi/g_Blo split.
// =====================================================================
__global__ void __launch_bounds__(512, 1)
lstm_kernel(const float* __restrict__ Whh) {
    __shared__ float partA[16][32];

    const int tid = threadIdx.x;
    const int w   = tid >> 5;
    const int l   = tid & 31;
    const int j   = tid & 7;
    const int c   = tid >> 3;
    const int b   = blockIdx.x;
    const int jg  = b * 8 + j;

    float creg = 0.f;

    unsigned long long wreg2[4][8];
#pragma unroll
    for (int g = 0; g < 4; g++) {
        const char* p = (const char*)(Whh + (size_t)(g * H_DIM + jg) * H_DIM + c * 16);
#pragma unroll
        for (int q = 0; q < 4; q++)
            ld2u64(p + q * 16, wreg2[g][2*q], wreg2[g][2*q+1]);
    }
    __syncthreads();

    for (int t = 0; t < T_STEPS; t++) {
        float xgv = 0.f;
        if (tid < 32)
            xgv = __ldcg(&g_Xg[t * NGATE + b * 32 + tid]);

        unsigned long long hv2[8];
        {
            const char* hp = (const char*)(g_hpub + t * H_DIM + c * 16);
#pragma unroll
            for (int q = 0; q < 4; q++)
                ld2u64_cg(hp + q * 16, hv2[2*q], hv2[2*q+1]);
        }
        float part[4];
#pragma unroll
        for (int g = 0; g < 4; g++) {
            unsigned long long acc = 0ull;
#pragma unroll
            for (int i = 0; i < 8; i++) fma2(acc, wreg2[g][i], hv2[i]);
            part[g] = sum2(acc);
        }
#pragma unroll
        for (int g = 0; g < 4; g++) {
            part[g] += __shfl_xor_sync(0xffffffffu, part[g], 8);
            part[g] += __shfl_xor_sync(0xffffffffu, part[g], 16);
        }
        if (l < 8) {
#pragma unroll
            for (int g = 0; g < 4; g++) partA[w][g * 8 + l] = part[g];
        }
        __syncthreads();                          // sync1

        if (tid < 32) {
            float s = xgv;
#pragma unroll
            for (int ww = 0; ww < 16; ww++) s += partA[ww][tid];

            const int jj = tid & 7;
            float sf = __shfl_sync(0xffffffffu, s, jj + 8);
            float sg = __shfl_sync(0xffffffffu, s, jj + 16);
            float so = __shfl_sync(0xffffffffu, s, jj + 24);

            if (tid < 8) {
                float ii = sigmoidf_(s);
                float ff = sigmoidf_(sf);
                float gg = tanhf_(sg);
                float oo = sigmoidf_(so);
                float cc = ff * creg + ii * gg;
                creg = cc;
                float hn = oo * tanhf_(cc);
                g_hpub[(t + 1) * H_DIM + b * 8 + tid] = hn;
            }
            __syncwarp();
            if (tid == 0) {
                asm volatile("red.release.gpu.global.add.u32 [%0], 1;"
                             :: "l"(&g_cnt) : "memory");
            }
        } else if (tid == 32) {
            // relaxed spin (cheap polls), single acquire after detection
            const unsigned int target = (unsigned)NBLK * (unsigned)(t + 1);
            unsigned int v;
            do {
                asm volatile("ld.relaxed.gpu.u32 %0, [%1];"
                             : "=r"(v) : "l"(&g_cnt) : "memory");
            } while (v < target);
            asm volatile("ld.acquire.gpu.u32 %0, [%1];"
                         : "=r"(v) : "l"(&g_cnt) : "memory");
        }
        __syncthreads();                          // sync_final
    }

    // ---- tail: split hs rows (g_hpub 1..64) -> g_Bhi/g_Blo, pre-swizzled ----
    {
        int idx = b * 512 + tid;          // 0..65535
        int t = idx >> 10;
        int e = idx & 1023;
        int cc2 = e >> 6, ee = e & 63;
        float v = __ldcg(&g_hpub[(t + 1) * H_DIM + e]);
        __nv_bfloat16 hb = __float2bfloat16(v);
        float hf = __bfloat162float(hb);
        __nv_bfloat16 lb = __float2bfloat16(v - hf);
        size_t dst = ((size_t)t * 16 + cc2) * 64 + (((ee >> 3) ^ (t & 7)) << 3) + (ee & 7);
        g_Bhi[dst] = hb;
        g_Blo[dst] = lb;
    }
}

// =====================================================================
// K3: fc GEMM — A fused-convert (single f32 buffer), B pure cp.async of
// pre-split bf16 (double-buffered). Per-bp B loading (low reg pressure).
// =====================================================================
#define FO_AF32   0
#define FO_AHI    32768
#define FO_ALO    49152
#define FO_BHI(b) (65536 + (b) * 16384)
#define FO_BLO(b) (65536 + (b) * 16384 + 8192)
#define FC_SMEM2  98304

__global__ void __launch_bounds__(128, 2)
fc_mma_kernel(const float* __restrict__ fcW, const float* __restrict__ fcb,
              float* __restrict__ out) {
    extern __shared__ __align__(1024) char smem[];
    const uint32_t sb = smem_u32(smem);

    const int tid  = threadIdx.x;
    const int wid  = tid >> 5;
    const int lane = tid & 31;
    const int vbase = blockIdx.x * FC_M;
    const int m0 = wid * 32;

    const int a_row  = m0 + (lane & 15);
    const uint32_t a_roff = (uint32_t)a_row * 128;
    const uint32_t a_xor  = (uint32_t)(a_row & 7) << 4;
    const uint32_t a_kh   = (uint32_t)(lane >> 4) * 16;
    const int b_rsub = (lane & 7) + ((lane >> 4) & 1) * 8;
    const uint32_t b_xor = (uint32_t)(lane & 7) << 4;
    const uint32_t b_kh  = (uint32_t)((lane >> 3) & 1) * 16;

    float acc[2][8][4];
#pragma unroll
    for (int mt = 0; mt < 2; mt++)
#pragma unroll
        for (int nt = 0; nt < 8; nt++)
#pragma unroll
            for (int q = 0; q < 4; q++) acc[mt][nt][q] = 0.f;

    auto issueAB = [&](int c) {
#pragma unroll
        for (int p = 0; p < 16; p++) {           // A: 2048 x 16B fp32
            int idx = tid + p * 128;
            int row = idx >> 4, seg = idx & 15;
            const char* src = (const char*)(fcW + (size_t)(vbase + row) * E_DIM + c * 64)
                              + seg * 16;
            CP16(sb + FO_AF32 + (uint32_t)(row * 256 + seg * 16), src);
        }
        const int buf = c & 1;
#pragma unroll
        for (int p = 0; p < 8; p++) {            // B: 1024 x 16B bf16 (hi+lo)
            int idx = tid + p * 128;
            int hl  = idx >> 9;
            int row = (idx >> 3) & 63;
            int seg = idx & 7;
            const char* src = (const char*)(hl ? g_Blo : g_Bhi)
                + (((size_t)row * 16 + c) * 128 + seg * 16);
            uint32_t dst = sb + (hl ? FO_BLO(buf) : FO_BHI(buf)) + row * 128 + seg * 16;
            CP16(dst, src);
        }
        CP_COMMIT();
    };

    issueAB(0);

    for (int c = 0; c < FC_NCH; c++) {
        CP_WAIT(0);
        __syncthreads();

        {
            const char* af = smem + FO_AF32;
#pragma unroll
            for (int p = 0; p < 32; p++) {
                int fidx = tid + p * 128;
                int row = fidx >> 5, kp = fidx & 31;
                float2 a = *(const float2*)(af + row * 256 + kp * 8);
                uint32_t hi, lo; split2(a, hi, lo);
                uint32_t off = SWZ((uint32_t)(row * 128 + kp * 4));
                *(uint32_t*)(smem + FO_AHI + off) = hi;
                *(uint32_t*)(smem + FO_ALO + off) = lo;
            }
        }
        __syncthreads();

        if (c + 1 < FC_NCH) issueAB(c + 1);

        const uint32_t sAhi = sb + FO_AHI, sAlo = sb + FO_ALO;
        const uint32_t sBhi = sb + FO_BHI(c & 1), sBlo = sb + FO_BLO(c & 1);
#pragma unroll
        for (int ks = 0; ks < 4; ks++) {
            const uint32_t akb = (uint32_t)(ks * 32) + a_kh;
            const uint32_t bkb = (uint32_t)(ks * 32) + b_kh;

            uint32_t ah[2][4], al[2][4];
#pragma unroll
            for (int mt = 0; mt < 2; mt++) {
                uint32_t off = a_roff + (uint32_t)(mt * 16 * 128) + (akb ^ a_xor);
                LDM_X4(ah[mt], sAhi + off);
                LDM_X4(al[mt], sAlo + off);
            }
#pragma unroll
            for (int bp = 0; bp < 4; bp++) {
                uint32_t n = (uint32_t)(bp * 16 + b_rsub);
                uint32_t off = n * 128 + (bkb ^ b_xor);
                uint32_t bh[4], bl[4];
                LDM_X4(bh, sBhi + off);
                LDM_X4(bl, sBlo + off);
#pragma unroll
                for (int mt = 0; mt < 2; mt++)
#pragma unroll
                    for (int sub = 0; sub < 2; sub++) {
                        const int nt = bp * 2 + sub, sel = sub * 2;
                        MMA16816(acc[mt][nt], ah[mt], bh[sel], bh[sel + 1]);
                        MMA16816(acc[mt][nt], al[mt], bh[sel], bh[sel + 1]);
                        MMA16816(acc[mt][nt], ah[mt], bl[sel], bl[sel + 1]);
                    }
            }
        }
    }

    const int g  = lane >> 2;
    const int t4 = lane & 3;
#pragma unroll
    for (int mt = 0; mt < 2; mt++) {
        int v0 = vbase + m0 + mt * 16 + g;
        float bv0 = fcb[v0];
        float bv8 = fcb[v0 + 8];
#pragma unroll
        for (int nt = 0; nt < 8; nt++) {
            int t0 = nt * 8 + t4 * 2;
            out[(size_t)t0 * VOC + v0]           = acc[mt][nt][0] + bv0;
            out[(size_t)(t0 + 1) * VOC + v0]     = acc[mt][nt][1] + bv0;
            out[(size_t)t0 * VOC + v0 + 8]       = acc[mt][nt][2] + bv8;
            out[(size_t)(t0 + 1) * VOC + v0 + 8] = acc[mt][nt][3] + bv8;
        }
    }
}

// =====================================================================
// launch
// =====================================================================
extern "C" void kernel_launch(void* const* d_in, const int* in_sizes, int n_in,
                              void* d_out, int out_size) {
    const int*   captions = (const int*)  d_in[0];
    const float* features = (const float*)d_in[1];
    const float* etab     = (const float*)d_in[2];
    const float* W_ih     = (const float*)d_in[3];
    const float* W_hh     = (const float*)d_in[4];
    const float* b_ih     = (const float*)d_in[5];
    const float* b_hh     = (const float*)d_in[6];
    const float* fc_W     = (const float*)d_in[7];
    const float* fc_b     = (const float*)d_in[8];
    float* out = (float*)d_out;

    cudaFuncSetAttribute(xg_mma_kernel,
                         cudaFuncAttributeMaxDynamicSharedMemorySize, XG_SMEM);
    cudaFuncSetAttribute(fc_mma_kernel,
                         cudaFuncAttributeMaxDynamicSharedMemorySize, FC_SMEM2);

    prep_kernel<<<T_STEPS, 256>>>(captions, features, etab);
    xg_mma_kernel<<<NGATE / FC_M, 128, XG_SMEM>>>(W_ih, b_ih, b_hh);
    lstm_kernel<<<NBLK, 512>>>(W_hh);
    fc_mma_kernel<<<VOC / FC_M, 128, FC_SMEM2>>>(fc_W, fc_b, out);
}

// round 16
// speedup vs baseline: 1.5368x; 1.0488x over previous
#include <cuda_runtime.h>
#include <cuda_bf16.h>
#include <cstdint>
#include <cstdio>

#define E_DIM 1024
#define H_DIM 1024
#define VOC   32000
#define T_STEPS 64
#define NBLK  128
#define NGATE 4096

// -------- device scratch --------
__device__ float g_X[T_STEPS * E_DIM];
__device__ float g_hpub[(T_STEPS + 1) * H_DIM];
__device__ float g_Xg[T_STEPS * NGATE];
__device__ unsigned int g_cnt;
// hs pre-split to bf16 hi/lo, pre-swizzled (lstm tail)
__device__ __nv_bfloat16 g_Bhi[T_STEPS * H_DIM];
__device__ __nv_bfloat16 g_Blo[T_STEPS * H_DIM];

__device__ __forceinline__ float sigmoidf_(float x) { return 1.f / (1.f + __expf(-x)); }
__device__ __forceinline__ float tanhf_(float x) {
    return __fdividef(2.f, 1.f + __expf(-2.f * x)) - 1.f;
}

// ---- packed f32x2 helpers ----
__device__ __forceinline__ void fma2(unsigned long long& d,
                                     unsigned long long a, unsigned long long b) {
    asm("fma.rn.f32x2 %0, %1, %2, %0;" : "+l"(d) : "l"(a), "l"(b));
}
__device__ __forceinline__ float sum2(unsigned long long v) {
    float lo, hi;
    asm("mov.b64 {%0, %1}, %2;" : "=f"(lo), "=f"(hi) : "l"(v));
    return lo + hi;
}
__device__ __forceinline__ void ld2u64(const void* p, unsigned long long& a,
                                       unsigned long long& b) {
    asm("ld.global.v2.u64 {%0, %1}, [%2];" : "=l"(a), "=l"(b) : "l"(p));
}
__device__ __forceinline__ void ld2u64_cg(const void* p, unsigned long long& a,
                                          unsigned long long& b) {
    asm("ld.global.cg.v2.u64 {%0, %1}, [%2];" : "=l"(a), "=l"(b) : "l"(p));
}

// =====================================================================
// K0: build X, init h row 0 + counter
// =====================================================================
__global__ void prep_kernel(const int* __restrict__ captions,
                            const float* __restrict__ features,
                            const float* __restrict__ etab) {
    int t = blockIdx.x;
    const float* src = (t == 0) ? features : (etab + (size_t)captions[t - 1] * E_DIM);
    for (int k = threadIdx.x; k < E_DIM; k += blockDim.x)
        g_X[t * E_DIM + k] = src[k];
    if (t == 0) {
        for (int k = threadIdx.x; k < H_DIM; k += blockDim.x) g_hpub[k] = 0.f;
        if (threadIdx.x == 0) g_cnt = 0u;
    }
}

// ======================= shared GEMM helpers =========================
#define FC_M    128
#define FC_NCH  16
#define SWZ(x) ((x) ^ (((x) >> 3) & 0x70))

__device__ __forceinline__ uint32_t smem_u32(const void* p) {
    uint32_t a;
    asm("{ .reg .u64 t; cvta.to.shared.u64 t, %1; cvt.u32.u64 %0, t; }" : "=r"(a) : "l"(p));
    return a;
}

__device__ __forceinline__ void split2(float2 a, uint32_t& hi, uint32_t& lo) {
    __nv_bfloat162 h = __float22bfloat162_rn(a);
    float2 f = __bfloat1622float2(h);
    __nv_bfloat162 l2 = __float22bfloat162_rn(make_float2(a.x - f.x, a.y - f.y));
    hi = *reinterpret_cast<uint32_t*>(&h);
    lo = *reinterpret_cast<uint32_t*>(&l2);
}

#define CP16(dst, src) \
    asm volatile("cp.async.cg.shared.global [%0], [%1], 16;" :: "r"(dst), "l"(src) : "memory")
#define CP_COMMIT() asm volatile("cp.async.commit_group;" ::: "memory")
#define CP_WAIT(n)  asm volatile("cp.async.wait_group %0;" :: "n"(n) : "memory")

#define LDM_X4(r, a)                                                          \
    asm volatile("ldmatrix.sync.aligned.m8n8.x4.shared.b16 {%0,%1,%2,%3}, [%4];" \
        : "=r"((r)[0]), "=r"((r)[1]), "=r"((r)[2]), "=r"((r)[3]) : "r"(a))

#define MMA16816(d, a, b0, b1)                                                \
    asm volatile("mma.sync.aligned.m16n8k16.row.col.f32.bf16.bf16.f32 "       \
        "{%0,%1,%2,%3},{%4,%5,%6,%7},{%8,%9},{%0,%1,%2,%3};"                  \
        : "+f"((d)[0]), "+f"((d)[1]), "+f"((d)[2]), "+f"((d)[3])              \
        : "r"((a)[0]), "r"((a)[1]), "r"((a)[2]), "r"((a)[3]),                 \
          "r"(b0), "r"(b1))

// =====================================================================
// K1: Xg = X @ W_ih^T + bias (32 CTAs) — proven fused-convert body.
// =====================================================================
#define XGO_AF32(b) ((b) * 32768)
#define XGO_AHI     65536
#define XGO_ALO     81920
#define XGO_BHI     98304
#define XGO_BLO     106496
#define XG_SMEM     114688

__device__ __forceinline__ int xg_dst(int r, int t) {
    return t * NGATE + (((r & 1023) >> 3) << 5) + ((r >> 10) << 3) + (r & 7);
}

__global__ void __launch_bounds__(128, 2)
xg_mma_kernel(const float* __restrict__ Wih,
              const float* __restrict__ bih, const float* __restrict__ bhh) {
    extern __shared__ __align__(1024) char smem[];
    const uint32_t sb = smem_u32(smem);

    const int tid  = threadIdx.x;
    const int wid  = tid >> 5;
    const int lane = tid & 31;
    const int vbase = blockIdx.x * FC_M;
    const int m0 = wid * 32;

    const int a_row  = m0 + (lane & 15);
    const uint32_t a_roff = (uint32_t)a_row * 128;
    const uint32_t a_xor  = (uint32_t)(a_row & 7) << 4;
    const uint32_t a_kh   = (uint32_t)(lane >> 4) * 16;
    const int b_rsub = (lane & 7) + ((lane >> 4) & 1) * 8;
    const uint32_t b_xor = (uint32_t)(lane & 7) << 4;
    const uint32_t b_kh  = (uint32_t)((lane >> 3) & 1) * 16;

    float acc[2][8][4];
#pragma unroll
    for (int mt = 0; mt < 2; mt++)
#pragma unroll
        for (int nt = 0; nt < 8; nt++)
#pragma unroll
            for (int q = 0; q < 4; q++) acc[mt][nt][q] = 0.f;

    auto issue = [&](int c) {
        const uint32_t dbase = sb + XGO_AF32(c & 1);
#pragma unroll
        for (int p = 0; p < 16; p++) {
            int idx = tid + p * 128;
            int row = idx >> 4, seg = idx & 15;
            const char* src = (const char*)(Wih + (size_t)(vbase + row) * E_DIM + c * 64)
                              + seg * 16;
            CP16(dbase + (uint32_t)(row * 256 + seg * 16), src);
        }
        CP_COMMIT();
    };

    issue(0);
    issue(1);

    for (int c = 0; c < FC_NCH; c++) {
        if (c < FC_NCH - 1) { CP_WAIT(1); } else { CP_WAIT(0); }
        __syncthreads();

        {
            const char* af = smem + XGO_AF32(c & 1);
#pragma unroll
            for (int p = 0; p < 32; p++) {
                int fidx = tid + p * 128;
                int row = fidx >> 5, kp = fidx & 31;
                float2 a = *(const float2*)(af + row * 256 + kp * 8);
                uint32_t hi, lo; split2(a, hi, lo);
                uint32_t off = SWZ((uint32_t)(row * 128 + kp * 4));
                *(uint32_t*)(smem + XGO_AHI + off) = hi;
                *(uint32_t*)(smem + XGO_ALO + off) = lo;
            }
        }
        {
#pragma unroll
            for (int p = 0; p < 16; p++) {
                int fidx = tid + p * 128;
                int row = fidx >> 5, kp = fidx & 31;
                float2 a = *(const float2*)(g_X + row * E_DIM + c * 64 + kp * 2);
                uint32_t hi, lo; split2(a, hi, lo);
                uint32_t off = SWZ((uint32_t)(row * 128 + kp * 4));
                *(uint32_t*)(smem + XGO_BHI + off) = hi;
                *(uint32_t*)(smem + XGO_BLO + off) = lo;
            }
        }
        __syncthreads();

        if (c + 2 < FC_NCH) issue(c + 2);

        const uint32_t sAhi = sb + XGO_AHI, sAlo = sb + XGO_ALO;
        const uint32_t sBhi = sb + XGO_BHI, sBlo = sb + XGO_BLO;
#pragma unroll
        for (int ks = 0; ks < 4; ks++) {
            const uint32_t akb = (uint32_t)(ks * 32) + a_kh;
            const uint32_t bkb = (uint32_t)(ks * 32) + b_kh;

            uint32_t ah[2][4], al[2][4];
#pragma unroll
            for (int mt = 0; mt < 2; mt++) {
                uint32_t off = a_roff + (uint32_t)(mt * 16 * 128) + (akb ^ a_xor);
                LDM_X4(ah[mt], sAhi + off);
                LDM_X4(al[mt], sAlo + off);
            }
#pragma unroll
            for (int bp = 0; bp < 4; bp++) {
                uint32_t n = (uint32_t)(bp * 16 + b_rsub);
                uint32_t off = n * 128 + (bkb ^ b_xor);
                uint32_t bh[4], bl[4];
                LDM_X4(bh, sBhi + off);
                LDM_X4(bl, sBlo + off);
#pragma unroll
                for (int mt = 0; mt < 2; mt++)
#pragma unroll
                    for (int sub = 0; sub < 2; sub++) {
                        const int nt = bp * 2 + sub, sel = sub * 2;
                        MMA16816(acc[mt][nt], ah[mt], bh[sel], bh[sel + 1]);
                        MMA16816(acc[mt][nt], al[mt], bh[sel], bh[sel + 1]);
                        MMA16816(acc[mt][nt], ah[mt], bl[sel], bl[sel + 1]);
                    }
            }
        }
    }

    const int g  = lane >> 2;
    const int t4 = lane & 3;
#pragma unroll
    for (int mt = 0; mt < 2; mt++) {
        int r0 = vbase + m0 + mt * 16 + g;
        float bv0 = bih[r0] + bhh[r0];
        float bv8 = bih[r0 + 8] + bhh[r0 + 8];
#pragma unroll
        for (int nt = 0; nt < 8; nt++) {
            int t0 = nt * 8 + t4 * 2;
            g_Xg[xg_dst(r0,     t0)]     = acc[mt][nt][0] + bv0;
            g_Xg[xg_dst(r0,     t0 + 1)] = acc[mt][nt][1] + bv0;
            g_Xg[xg_dst(r0 + 8, t0)]     = acc[mt][nt][2] + bv8;
            g_Xg[xg_dst(r0 + 8, t0 + 1)] = acc[mt][nt][3] + bv8;
        }
    }
}

// =====================================================================
// K2: persistent LSTM recurrence (R15-proven: relaxed poll + acquire).
// Tail: one-shot hs -> g_Bhi/g_Blo split.
// =====================================================================
__global__ void __launch_bounds__(512, 1)
lstm_kernel(const float* __restrict__ Whh) {
    __shared__ float partA[16][32];

    const int tid = threadIdx.x;
    const int w   = tid >> 5;
    const int l   = tid & 31;
    const int j   = tid & 7;
    const int c   = tid >> 3;
    const int b   = blockIdx.x;
    const int jg  = b * 8 + j;

    float creg = 0.f;

    unsigned long long wreg2[4][8];
#pragma unroll
    for (int g = 0; g < 4; g++) {
        const char* p = (const char*)(Whh + (size_t)(g * H_DIM + jg) * H_DIM + c * 16);
#pragma unroll
        for (int q = 0; q < 4; q++)
            ld2u64(p + q * 16, wreg2[g][2*q], wreg2[g][2*q+1]);
    }
    __syncthreads();

    for (int t = 0; t < T_STEPS; t++) {
        float xgv = 0.f;
        if (tid < 32)
            xgv = __ldcg(&g_Xg[t * NGATE + b * 32 + tid]);

        unsigned long long hv2[8];
        {
            const char* hp = (const char*)(g_hpub + t * H_DIM + c * 16);
#pragma unroll
            for (int q = 0; q < 4; q++)
                ld2u64_cg(hp + q * 16, hv2[2*q], hv2[2*q+1]);
        }
        float part[4];
#pragma unroll
        for (int g = 0; g < 4; g++) {
            unsigned long long acc = 0ull;
#pragma unroll
            for (int i = 0; i < 8; i++) fma2(acc, wreg2[g][i], hv2[i]);
            part[g] = sum2(acc);
        }
#pragma unroll
        for (int g = 0; g < 4; g++) {
            part[g] += __shfl_xor_sync(0xffffffffu, part[g], 8);
            part[g] += __shfl_xor_sync(0xffffffffu, part[g], 16);
        }
        if (l < 8) {
#pragma unroll
            for (int g = 0; g < 4; g++) partA[w][g * 8 + l] = part[g];
        }
        __syncthreads();                          // sync1

        if (tid < 32) {
            float s = xgv;
#pragma unroll
            for (int ww = 0; ww < 16; ww++) s += partA[ww][tid];

            const int jj = tid & 7;
            float sf = __shfl_sync(0xffffffffu, s, jj + 8);
            float sg = __shfl_sync(0xffffffffu, s, jj + 16);
            float so = __shfl_sync(0xffffffffu, s, jj + 24);

            if (tid < 8) {
                float ii = sigmoidf_(s);
                float ff = sigmoidf_(sf);
                float gg = tanhf_(sg);
                float oo = sigmoidf_(so);
                float cc = ff * creg + ii * gg;
                creg = cc;
                float hn = oo * tanhf_(cc);
                g_hpub[(t + 1) * H_DIM + b * 8 + tid] = hn;
            }
            __syncwarp();
            if (tid == 0) {
                asm volatile("red.release.gpu.global.add.u32 [%0], 1;"
                             :: "l"(&g_cnt) : "memory");
            }
        } else if (tid == 32) {
            const unsigned int target = (unsigned)NBLK * (unsigned)(t + 1);
            unsigned int v;
            do {
                asm volatile("ld.relaxed.gpu.u32 %0, [%1];"
                             : "=r"(v) : "l"(&g_cnt) : "memory");
            } while (v < target);
            asm volatile("ld.acquire.gpu.u32 %0, [%1];"
                         : "=r"(v) : "l"(&g_cnt) : "memory");
        }
        __syncthreads();                          // sync_final
    }

    // ---- tail: split hs rows (g_hpub 1..64) -> g_Bhi/g_Blo, pre-swizzled ----
    {
        int idx = b * 512 + tid;          // 0..65535
        int t = idx >> 10;
        int e = idx & 1023;
        int cc2 = e >> 6, ee = e & 63;
        float v = __ldcg(&g_hpub[(t + 1) * H_DIM + e]);
        __nv_bfloat16 hb = __float2bfloat16(v);
        float hf = __bfloat162float(hb);
        __nv_bfloat16 lb = __float2bfloat16(v - hf);
        size_t dst = ((size_t)t * 16 + cc2) * 64 + (((ee >> 3) ^ (t & 7)) << 3) + (ee & 7);
        g_Bhi[dst] = hb;
        g_Blo[dst] = lb;
    }
}

// =====================================================================
// K3: fc GEMM — 256 threads/CTA (8 warps, m16 strip each): halves
// accumulator regs, doubles warps/SM. A fused-convert (single f32 buf),
// B cp.async of pre-split bf16 (double-buffered).
// =====================================================================
#define FO_AF32   0
#define FO_AHI    32768
#define FO_ALO    49152
#define FO_BHI(b) (65536 + (b) * 16384)
#define FO_BLO(b) (65536 + (b) * 16384 + 8192)
#define FC_SMEM2  98304

__global__ void __launch_bounds__(256, 2)
fc_mma_kernel(const float* __restrict__ fcW, const float* __restrict__ fcb,
              float* __restrict__ out) {
    extern __shared__ __align__(1024) char smem[];
    const uint32_t sb = smem_u32(smem);

    const int tid  = threadIdx.x;
    const int wid  = tid >> 5;            // 0..7
    const int lane = tid & 31;
    const int vbase = blockIdx.x * FC_M;
    const int m0 = wid * 16;              // m16 strip per warp

    const int a_row  = m0 + (lane & 15);
    const uint32_t a_roff = (uint32_t)a_row * 128;
    const uint32_t a_xor  = (uint32_t)(a_row & 7) << 4;
    const uint32_t a_kh   = (uint32_t)(lane >> 4) * 16;
    const int b_rsub = (lane & 7) + ((lane >> 4) & 1) * 8;
    const uint32_t b_xor = (uint32_t)(lane & 7) << 4;
    const uint32_t b_kh  = (uint32_t)((lane >> 3) & 1) * 16;

    float acc[8][4];
#pragma unroll
    for (int nt = 0; nt < 8; nt++)
#pragma unroll
        for (int q = 0; q < 4; q++) acc[nt][q] = 0.f;

    auto issueAB = [&](int c) {
#pragma unroll
        for (int p = 0; p < 8; p++) {            // A: 2048 x 16B fp32
            int idx = tid + p * 256;
            int row = idx >> 4, seg = idx & 15;
            const char* src = (const char*)(fcW + (size_t)(vbase + row) * E_DIM + c * 64)
                              + seg * 16;
            CP16(sb + FO_AF32 + (uint32_t)(row * 256 + seg * 16), src);
        }
        const int buf = c & 1;
#pragma unroll
        for (int p = 0; p < 4; p++) {            // B: 1024 x 16B bf16 (hi+lo)
            int idx = tid + p * 256;
            int hl  = idx >> 9;
            int row = (idx >> 3) & 63;
            int seg = idx & 7;
            const char* src = (const char*)(hl ? g_Blo : g_Bhi)
                + (((size_t)row * 16 + c) * 128 + seg * 16);
            uint32_t dst = sb + (hl ? FO_BLO(buf) : FO_BHI(buf)) + row * 128 + seg * 16;
            CP16(dst, src);
        }
        CP_COMMIT();
    };

    issueAB(0);

    for (int c = 0; c < FC_NCH; c++) {
        CP_WAIT(0);
        __syncthreads();

        // ---- convert A: f32 smem -> bf16 hi/lo smem (SW128) ----
        {
            const char* af = smem + FO_AF32;
#pragma unroll
            for (int p = 0; p < 16; p++) {
                int fidx = tid + p * 256;
                int row = fidx >> 5, kp = fidx & 31;
                float2 a = *(const float2*)(af + row * 256 + kp * 8);
                uint32_t hi, lo; split2(a, hi, lo);
                uint32_t off = SWZ((uint32_t)(row * 128 + kp * 4));
                *(uint32_t*)(smem + FO_AHI + off) = hi;
                *(uint32_t*)(smem + FO_ALO + off) = lo;
            }
        }
        __syncthreads();

        if (c + 1 < FC_NCH) issueAB(c + 1);

        const uint32_t sAhi = sb + FO_AHI, sAlo = sb + FO_ALO;
        const uint32_t sBhi = sb + FO_BHI(c & 1), sBlo = sb + FO_BLO(c & 1);
#pragma unroll
        for (int ks = 0; ks < 4; ks++) {
            const uint32_t akb = (uint32_t)(ks * 32) + a_kh;
            const uint32_t bkb = (uint32_t)(ks * 32) + b_kh;

            uint32_t ah[4], al[4];
            {
                uint32_t off = a_roff + (akb ^ a_xor);
                LDM_X4(ah, sAhi + off);
                LDM_X4(al, sAlo + off);
            }
#pragma unroll
            for (int bp = 0; bp < 4; bp++) {
                uint32_t n = (uint32_t)(bp * 16 + b_rsub);
                uint32_t off = n * 128 + (bkb ^ b_xor);
                uint32_t bh[4], bl[4];
                LDM_X4(bh, sBhi + off);
                LDM_X4(bl, sBlo + off);
#pragma unroll
                for (int sub = 0; sub < 2; sub++) {
                    const int nt = bp * 2 + sub, sel = sub * 2;
                    MMA16816(acc[nt], ah, bh[sel], bh[sel + 1]);
                    MMA16816(acc[nt], al, bh[sel], bh[sel + 1]);
                    MMA16816(acc[nt], ah, bl[sel], bl[sel + 1]);
                }
            }
        }
    }

    const int g  = lane >> 2;
    const int t4 = lane & 3;
    {
        int v0 = vbase + m0 + g;
        float bv0 = fcb[v0];
        float bv8 = fcb[v0 + 8];
#pragma unroll
        for (int nt = 0; nt < 8; nt++) {
            int t0 = nt * 8 + t4 * 2;
            out[(size_t)t0 * VOC + v0]           = acc[nt][0] + bv0;
            out[(size_t)(t0 + 1) * VOC + v0]     = acc[nt][1] + bv0;
            out[(size_t)t0 * VOC + v0 + 8]       = acc[nt][2] + bv8;
            out[(size_t)(t0 + 1) * VOC + v0 + 8] = acc[nt][3] + bv8;
        }
    }
}

// =====================================================================
// launch
// =====================================================================
extern "C" void kernel_launch(void* const* d_in, const int* in_sizes, int n_in,
                              void* d_out, int out_size) {
    const int*   captions = (const int*)  d_in[0];
    const float* features = (const float*)d_in[1];
    const float* etab     = (const float*)d_in[2];
    const float* W_ih     = (const float*)d_in[3];
    const float* W_hh     = (const float*)d_in[4];
    const float* b_ih     = (const float*)d_in[5];
    const float* b_hh     = (const float*)d_in[6];
    const float* fc_W     = (const float*)d_in[7];
    const float* fc_b     = (const float*)d_in[8];
    float* out = (float*)d_out;

    cudaFuncSetAttribute(xg_mma_kernel,
                         cudaFuncAttributeMaxDynamicSharedMemorySize, XG_SMEM);
    cudaFuncSetAttribute(fc_mma_kernel,
                         cudaFuncAttributeMaxDynamicSharedMemorySize, FC_SMEM2);

    prep_kernel<<<T_STEPS, 256>>>(captions, features, etab);
    xg_mma_kernel<<<NGATE / FC_M, 128, XG_SMEM>>>(W_ih, b_ih, b_hh);
    lstm_kernel<<<NBLK, 512>>>(W_hh);
    fc_mma_kernel<<<VOC / FC_M, 256, FC_SMEM2>>>(fc_W, fc_b, out);
}